// round 2
// baseline (speedup 1.0000x reference)
#include <cuda_runtime.h>
#include <math.h>

#define NN   100000
#define EE   1600000
#define FIN  256
#define HH   128
#define CC   10
#define SCAN_B 1024
#define NBLK ((NN + SCAN_B - 1) / SCAN_B)   // 98

// ---------------- scratch (no allocs allowed) ----------------
__device__ int   g_deg[NN];
__device__ int   g_local[NN];
__device__ int   g_bsum[NBLK];
__device__ int   g_boff[NBLK];
__device__ int   g_off[NN];
__device__ int   g_cursor[NN];
__device__ float g_dinv[NN];
__device__ int   g_csr[EE];
__device__ float g_h1[(size_t)NN * HH];   // 51.2 MB, L2-resident working set
__device__ float g_t[NN * CC];

// ---------------- degree / normalization ----------------
__global__ void k_zero_deg() {
    int i = blockIdx.x * blockDim.x + threadIdx.x;
    if (i < NN) g_deg[i] = 0;
}

__global__ void k_deg(const int* __restrict__ dst) {
    int e = blockIdx.x * blockDim.x + threadIdx.x;
    if (e < EE) atomicAdd(&g_deg[dst[e]], 1);
}

__global__ void k_dinv() {
    int i = blockIdx.x * blockDim.x + threadIdx.x;
    if (i < NN) g_dinv[i] = rsqrtf((float)(g_deg[i] + 1));  // +1 self loop
}

// ---------------- CSR build: scan + bucket fill ----------------
__global__ void k_scan1() {
    __shared__ int sh[SCAN_B];
    int tid = threadIdx.x;
    int i = blockIdx.x * SCAN_B + tid;
    int v = (i < NN) ? g_deg[i] : 0;
    sh[tid] = v;
    __syncthreads();
    for (int ofs = 1; ofs < SCAN_B; ofs <<= 1) {
        int t = (tid >= ofs) ? sh[tid - ofs] : 0;
        __syncthreads();
        sh[tid] += t;
        __syncthreads();
    }
    if (i < NN) g_local[i] = sh[tid] - v;     // exclusive
    if (tid == SCAN_B - 1) g_bsum[blockIdx.x] = sh[tid];
}

__global__ void k_scan2() {
    if (threadIdx.x == 0 && blockIdx.x == 0) {
        int acc = 0;
        for (int b = 0; b < NBLK; b++) { g_boff[b] = acc; acc += g_bsum[b]; }
    }
}

__global__ void k_finalize() {
    int i = blockIdx.x * blockDim.x + threadIdx.x;
    if (i < NN) {
        int o = g_local[i] + g_boff[i >> 10];
        g_off[i] = o;
        g_cursor[i] = o;
    }
}

__global__ void k_fill(const int* __restrict__ src, const int* __restrict__ dst) {
    int e = blockIdx.x * blockDim.x + threadIdx.x;
    if (e < EE) {
        int d = dst[e];
        int pos = atomicAdd(&g_cursor[d], 1);
        g_csr[pos] = src[e];
    }
}

// ---------------- GEMM1: h1 = x @ W1  (100000x256x128, fp32) ----------------
// BM=64, BN=128, BK=16, 256 threads, each thread 8x4 outputs.
__global__ void k_gemm1(const float* __restrict__ x, const float* __restrict__ W1) {
    __shared__ float As[64][16];
    __shared__ float Bs[16][128];
    int tid = threadIdx.x;
    int tx = tid & 31;          // N: col = tx*4
    int ty = tid >> 5;          // M: rows ty*8 .. ty*8+7
    int row_base = blockIdx.x * 64;

    float acc[8][4];
#pragma unroll
    for (int i = 0; i < 8; i++)
#pragma unroll
        for (int j = 0; j < 4; j++) acc[i][j] = 0.f;

    int ar = tid >> 2;          // 0..63
    int ac = (tid & 3) * 4;     // 0,4,8,12
    int gr = row_base + ar; if (gr >= NN) gr = NN - 1;

    for (int k0 = 0; k0 < FIN; k0 += 16) {
        float4 av = *reinterpret_cast<const float4*>(&x[(size_t)gr * FIN + k0 + ac]);
        *reinterpret_cast<float4*>(&As[ar][ac]) = av;
#pragma unroll
        for (int r = 0; r < 2; r++) {
            int f4 = tid + r * 256;           // 0..511
            int brow = f4 >> 5;               // 0..15
            int bcol = (f4 & 31) * 4;         // 0..124
            *reinterpret_cast<float4*>(&Bs[brow][bcol]) =
                *reinterpret_cast<const float4*>(&W1[(size_t)(k0 + brow) * HH + bcol]);
        }
        __syncthreads();
#pragma unroll
        for (int kk = 0; kk < 16; kk++) {
            float a[8];
#pragma unroll
            for (int i = 0; i < 8; i++) a[i] = As[ty * 8 + i][kk];
            float4 b = *reinterpret_cast<float4*>(&Bs[kk][tx * 4]);
#pragma unroll
            for (int i = 0; i < 8; i++) {
                acc[i][0] += a[i] * b.x;
                acc[i][1] += a[i] * b.y;
                acc[i][2] += a[i] * b.z;
                acc[i][3] += a[i] * b.w;
            }
        }
        __syncthreads();
    }
#pragma unroll
    for (int i = 0; i < 8; i++) {
        int row = row_base + ty * 8 + i;
        if (row < NN) {
            float4 v = make_float4(acc[i][0], acc[i][1], acc[i][2], acc[i][3]);
            *reinterpret_cast<float4*>(&g_h1[(size_t)row * HH + tx * 4]) = v;
        }
    }
}

// ---------------- fused: agg1 (gather) + b1 + relu + GEMM2 -> t ----------------
// one warp per node; lane covers 4 of the 128 hidden channels.
__global__ void k_agg1_gemm2(const float* __restrict__ b1, const float* __restrict__ W2) {
    __shared__ float sW2[CC][HH];   // transposed: [c][j], float4-readable rows
    int tid = threadIdx.x;
    for (int i = tid; i < HH * CC; i += blockDim.x) {
        int j = i / CC, c = i % CC;
        sW2[c][j] = W2[i];          // W2[j*CC + c]
    }
    __syncthreads();

    int lane = tid & 31;
    int node = blockIdx.x * 8 + (tid >> 5);   // grid = NN/8 exactly

    float di = g_dinv[node];
    int s0 = g_off[node];
    int cnt = g_deg[node];
    const float4* h1v = reinterpret_cast<const float4*>(g_h1);

    float4 acc = make_float4(0.f, 0.f, 0.f, 0.f);
    for (int k = 0; k < cnt; k++) {
        int s = g_csr[s0 + k];
        float nrm = g_dinv[s] * di;
        float4 v = h1v[s * (HH / 4) + lane];
        acc.x += v.x * nrm; acc.y += v.y * nrm;
        acc.z += v.z * nrm; acc.w += v.w * nrm;
    }
    {   // self loop
        float nrm = di * di;
        float4 v = h1v[node * (HH / 4) + lane];
        acc.x += v.x * nrm; acc.y += v.y * nrm;
        acc.z += v.z * nrm; acc.w += v.w * nrm;
    }
    float4 bb = reinterpret_cast<const float4*>(b1)[lane];
    float h0 = fmaxf(acc.x + bb.x, 0.f);
    float h1r = fmaxf(acc.y + bb.y, 0.f);
    float h2r = fmaxf(acc.z + bb.z, 0.f);
    float h3r = fmaxf(acc.w + bb.w, 0.f);

    float myval = 0.f;
#pragma unroll
    for (int c = 0; c < CC; c++) {
        float4 w = reinterpret_cast<float4*>(&sW2[c][0])[lane];
        float p = h0 * w.x + h1r * w.y + h2r * w.z + h3r * w.w;
#pragma unroll
        for (int m = 16; m; m >>= 1) p += __shfl_xor_sync(0xffffffffu, p, m);
        if (lane == c) myval = p;
    }
    if (lane < CC) g_t[node * CC + lane] = myval;
}

// ---------------- fused: agg2 (gather) + b2 + log_softmax -> out ----------------
__global__ void k_agg2_softmax(const float* __restrict__ b2, float* __restrict__ out) {
    int tid = threadIdx.x;
    int lane = tid & 31;
    int node = blockIdx.x * 8 + (tid >> 5);

    float di = g_dinv[node];
    int s0 = g_off[node];
    int cnt = g_deg[node];
    bool act = lane < CC;

    float acc = 0.f;
    for (int k = 0; k < cnt; k++) {
        int s = g_csr[s0 + k];            // broadcast load
        float nrm = g_dinv[s] * di;
        if (act) acc += nrm * g_t[s * CC + lane];
    }
    if (act) acc += di * di * g_t[node * CC + lane] + b2[lane];

    const float NEG_INF = __int_as_float(0xff800000u);
    float m = act ? acc : NEG_INF;
#pragma unroll
    for (int mk = 8; mk; mk >>= 1) m = fmaxf(m, __shfl_xor_sync(0xffffffffu, m, mk));
    float e = act ? expf(acc - m) : 0.f;
    float s = e;
#pragma unroll
    for (int mk = 8; mk; mk >>= 1) s += __shfl_xor_sync(0xffffffffu, s, mk);
    float lse = m + logf(s);
    if (act) out[node * CC + lane] = acc - lse;
}

// ---------------- launcher ----------------
extern "C" void kernel_launch(void* const* d_in, const int* in_sizes, int n_in,
                              void* d_out, int out_size) {
    const float* x  = (const float*)d_in[0];
    const int*   ei = (const int*)d_in[1];
    const float* W1 = (const float*)d_in[2];
    const float* b1 = (const float*)d_in[3];
    const float* W2 = (const float*)d_in[4];
    const float* b2 = (const float*)d_in[5];
    float* out = (float*)d_out;

    const int* src = ei;
    const int* dst = ei + EE;

    k_zero_deg<<<(NN + 255) / 256, 256>>>();
    k_deg<<<(EE + 255) / 256, 256>>>(dst);
    k_dinv<<<(NN + 255) / 256, 256>>>();
    k_scan1<<<NBLK, SCAN_B>>>();
    k_scan2<<<1, 32>>>();
    k_finalize<<<(NN + 255) / 256, 256>>>();
    k_fill<<<(EE + 255) / 256, 256>>>(src, dst);
    k_gemm1<<<(NN + 63) / 64, 256>>>(x, W1);
    k_agg1_gemm2<<<NN / 8, 256>>>(b1, W2);
    k_agg2_softmax<<<NN / 8, 256>>>(b2, out);
}

// round 3
// speedup vs baseline: 1.1010x; 1.1010x over previous
#include <cuda_runtime.h>
#include <cuda_bf16.h>
#include <mma.h>
#include <math.h>

using namespace nvcuda;

#define NN   100000
#define NPAD 100096                 // 782 * 128, pad for guard-free MMA epilogue
#define EE   1600000
#define FIN  256
#define HH   128
#define CC   10
#define SCAN_B 1024
#define NBLK ((NN + SCAN_B - 1) / SCAN_B)   // 98

// ---------------- scratch (no allocs allowed) ----------------
__device__ int   g_deg[NN];
__device__ int   g_local[NN];
__device__ int   g_bsum[NBLK];
__device__ int   g_boff[NBLK];
__device__ int   g_off[NN];
__device__ int   g_cursor[NN];
__device__ float g_dinv[NN];
__device__ int   g_csr[EE];
__device__ float g_h1[(size_t)NPAD * HH];   // 51.25 MB, L2-resident working set
__device__ float g_t[NN * CC];

// ---------------- degree / normalization ----------------
__global__ void k_zero_deg() {
    int i = blockIdx.x * blockDim.x + threadIdx.x;
    if (i < NN) g_deg[i] = 0;
}

__global__ void k_deg(const int* __restrict__ dst) {
    int e = blockIdx.x * blockDim.x + threadIdx.x;
    if (e < EE) atomicAdd(&g_deg[dst[e]], 1);
}

__global__ void k_dinv() {
    int i = blockIdx.x * blockDim.x + threadIdx.x;
    if (i < NN) g_dinv[i] = rsqrtf((float)(g_deg[i] + 1));  // +1 self loop
}

// ---------------- CSR build: scan + bucket fill ----------------
__global__ void k_scan1() {
    __shared__ int sh[SCAN_B];
    int tid = threadIdx.x;
    int i = blockIdx.x * SCAN_B + tid;
    int v = (i < NN) ? g_deg[i] : 0;
    sh[tid] = v;
    __syncthreads();
    for (int ofs = 1; ofs < SCAN_B; ofs <<= 1) {
        int t = (tid >= ofs) ? sh[tid - ofs] : 0;
        __syncthreads();
        sh[tid] += t;
        __syncthreads();
    }
    if (i < NN) g_local[i] = sh[tid] - v;     // exclusive
    if (tid == SCAN_B - 1) g_bsum[blockIdx.x] = sh[tid];
}

__global__ void k_scan2() {
    if (threadIdx.x == 0 && blockIdx.x == 0) {
        int acc = 0;
        for (int b = 0; b < NBLK; b++) { g_boff[b] = acc; acc += g_bsum[b]; }
    }
}

__global__ void k_finalize() {
    int i = blockIdx.x * blockDim.x + threadIdx.x;
    if (i < NN) {
        int o = g_local[i] + g_boff[i >> 10];
        g_off[i] = o;
        g_cursor[i] = o;
    }
}

__global__ void k_fill(const int* __restrict__ src, const int* __restrict__ dst) {
    int e = blockIdx.x * blockDim.x + threadIdx.x;
    if (e < EE) {
        int d = dst[e];
        int pos = atomicAdd(&g_cursor[d], 1);
        g_csr[pos] = src[e];
    }
}

// ---------------- GEMM1: h1 = x @ W1 via bf16x3 tensor-core split ----------------
// a = a_hi + a_lo (bf16 each); C += Ah*Bh + Ah*Bl + Al*Bh  (fp32 accumulate)
// BM=128, BN=128, BK=32; 256 threads = 8 warps (4m x 2n); warp tile 32x64.
__device__ __forceinline__ void split2(float v, __nv_bfloat16& h, __nv_bfloat16& l) {
    h = __float2bfloat16(v);
    l = __float2bfloat16(v - __bfloat162float(h));
}

__global__ void __launch_bounds__(256) k_gemm1(const float* __restrict__ x,
                                               const float* __restrict__ W1) {
    const int LDA = 40;   // 32 + 8 pad (elems)
    const int LDB = 136;  // 128 + 8 pad
    __shared__ __nv_bfloat16 Ah[128 * LDA];
    __shared__ __nv_bfloat16 Al[128 * LDA];
    __shared__ __nv_bfloat16 Bh[32 * LDB];
    __shared__ __nv_bfloat16 Bl[32 * LDB];

    int tid = threadIdx.x;
    int wid = tid >> 5;
    int wm = wid >> 1;        // 0..3
    int wn = wid & 1;         // 0..1
    int row0 = blockIdx.x * 128;

    wmma::fragment<wmma::accumulator, 16, 16, 16, float> c[2][4];
#pragma unroll
    for (int i = 0; i < 2; i++)
#pragma unroll
        for (int j = 0; j < 4; j++) wmma::fill_fragment(c[i][j], 0.f);

    for (int k0 = 0; k0 < FIN; k0 += 32) {
        // A tile: 128 rows x 32 cols = 1024 float4 loads, 4 per thread
#pragma unroll
        for (int r = 0; r < 4; r++) {
            int f4 = tid + r * 256;         // 0..1023
            int row = f4 >> 3;              // 0..127
            int c4 = (f4 & 7) * 4;          // 0..28
            int gr = row0 + row; if (gr >= NN) gr = NN - 1;
            float4 v = *reinterpret_cast<const float4*>(&x[(size_t)gr * FIN + k0 + c4]);
            __nv_bfloat16 h, l;
            split2(v.x, h, l); Ah[row*LDA + c4 + 0] = h; Al[row*LDA + c4 + 0] = l;
            split2(v.y, h, l); Ah[row*LDA + c4 + 1] = h; Al[row*LDA + c4 + 1] = l;
            split2(v.z, h, l); Ah[row*LDA + c4 + 2] = h; Al[row*LDA + c4 + 2] = l;
            split2(v.w, h, l); Ah[row*LDA + c4 + 3] = h; Al[row*LDA + c4 + 3] = l;
        }
        // B tile: 32 rows x 128 cols = 1024 float4 loads, 4 per thread
#pragma unroll
        for (int r = 0; r < 4; r++) {
            int f4 = tid + r * 256;
            int row = f4 >> 5;              // 0..31
            int c4 = (f4 & 31) * 4;         // 0..124
            float4 v = *reinterpret_cast<const float4*>(&W1[(size_t)(k0 + row) * HH + c4]);
            __nv_bfloat16 h, l;
            split2(v.x, h, l); Bh[row*LDB + c4 + 0] = h; Bl[row*LDB + c4 + 0] = l;
            split2(v.y, h, l); Bh[row*LDB + c4 + 1] = h; Bl[row*LDB + c4 + 1] = l;
            split2(v.z, h, l); Bh[row*LDB + c4 + 2] = h; Bl[row*LDB + c4 + 2] = l;
            split2(v.w, h, l); Bh[row*LDB + c4 + 3] = h; Bl[row*LDB + c4 + 3] = l;
        }
        __syncthreads();
#pragma unroll
        for (int kk = 0; kk < 32; kk += 16) {
            wmma::fragment<wmma::matrix_a, 16, 16, 16, __nv_bfloat16, wmma::row_major> ah[2], al[2];
            wmma::fragment<wmma::matrix_b, 16, 16, 16, __nv_bfloat16, wmma::row_major> bh[4], bl[4];
#pragma unroll
            for (int i = 0; i < 2; i++) {
                wmma::load_matrix_sync(ah[i], &Ah[(wm*32 + i*16)*LDA + kk], LDA);
                wmma::load_matrix_sync(al[i], &Al[(wm*32 + i*16)*LDA + kk], LDA);
            }
#pragma unroll
            for (int j = 0; j < 4; j++) {
                wmma::load_matrix_sync(bh[j], &Bh[kk*LDB + wn*64 + j*16], LDB);
                wmma::load_matrix_sync(bl[j], &Bl[kk*LDB + wn*64 + j*16], LDB);
            }
#pragma unroll
            for (int i = 0; i < 2; i++)
#pragma unroll
                for (int j = 0; j < 4; j++) {
                    wmma::mma_sync(c[i][j], ah[i], bh[j], c[i][j]);
                    wmma::mma_sync(c[i][j], ah[i], bl[j], c[i][j]);
                    wmma::mma_sync(c[i][j], al[i], bh[j], c[i][j]);
                }
        }
        __syncthreads();
    }
#pragma unroll
    for (int i = 0; i < 2; i++)
#pragma unroll
        for (int j = 0; j < 4; j++)
            wmma::store_matrix_sync(
                &g_h1[(size_t)(row0 + wm*32 + i*16) * HH + wn*64 + j*16],
                c[i][j], HH, wmma::mem_row_major);
}

// ---------------- fused: agg1 (gather) + b1 + relu + GEMM2 -> t ----------------
// one warp per node; lane covers 4 of the 128 hidden channels.
__global__ void k_agg1_gemm2(const float* __restrict__ b1, const float* __restrict__ W2) {
    __shared__ float sW2[CC][HH];   // transposed: [c][j], float4-readable rows
    int tid = threadIdx.x;
    for (int i = tid; i < HH * CC; i += blockDim.x) {
        int j = i / CC, c = i % CC;
        sW2[c][j] = W2[i];          // W2[j*CC + c]
    }
    __syncthreads();

    int lane = tid & 31;
    int node = blockIdx.x * 8 + (tid >> 5);   // grid = NN/8 exactly

    float di = g_dinv[node];
    int s0 = g_off[node];
    int cnt = g_deg[node];
    const float4* h1v = reinterpret_cast<const float4*>(g_h1);

    float4 acc = make_float4(0.f, 0.f, 0.f, 0.f);
    if (cnt > 0) {
        // 1-deep software pipeline: next edge's index/norm loads overlap
        // the current edge's 512B h1-row fetch.
        int s = g_csr[s0];
        float nrm = g_dinv[s] * di;
        for (int k = 1; k < cnt; k++) {
            int s2 = g_csr[s0 + k];
            float nrm2 = g_dinv[s2] * di;
            float4 v = h1v[s * (HH / 4) + lane];
            acc.x += v.x * nrm; acc.y += v.y * nrm;
            acc.z += v.z * nrm; acc.w += v.w * nrm;
            s = s2; nrm = nrm2;
        }
        float4 v = h1v[s * (HH / 4) + lane];
        acc.x += v.x * nrm; acc.y += v.y * nrm;
        acc.z += v.z * nrm; acc.w += v.w * nrm;
    }
    {   // self loop
        float nrm = di * di;
        float4 v = h1v[node * (HH / 4) + lane];
        acc.x += v.x * nrm; acc.y += v.y * nrm;
        acc.z += v.z * nrm; acc.w += v.w * nrm;
    }
    float4 bb = reinterpret_cast<const float4*>(b1)[lane];
    float h0  = fmaxf(acc.x + bb.x, 0.f);
    float h1r = fmaxf(acc.y + bb.y, 0.f);
    float h2r = fmaxf(acc.z + bb.z, 0.f);
    float h3r = fmaxf(acc.w + bb.w, 0.f);

    float myval = 0.f;
#pragma unroll
    for (int c = 0; c < CC; c++) {
        float4 w = reinterpret_cast<float4*>(&sW2[c][0])[lane];
        float p = h0 * w.x + h1r * w.y + h2r * w.z + h3r * w.w;
#pragma unroll
        for (int m = 16; m; m >>= 1) p += __shfl_xor_sync(0xffffffffu, p, m);
        if (lane == c) myval = p;
    }
    if (lane < CC) g_t[node * CC + lane] = myval;
}

// ---------------- fused: agg2 (gather) + b2 + log_softmax -> out ----------------
__global__ void k_agg2_softmax(const float* __restrict__ b2, float* __restrict__ out) {
    int tid = threadIdx.x;
    int lane = tid & 31;
    int node = blockIdx.x * 8 + (tid >> 5);

    float di = g_dinv[node];
    int s0 = g_off[node];
    int cnt = g_deg[node];
    bool act = lane < CC;

    float acc = 0.f;
    for (int k = 0; k < cnt; k++) {
        int s = g_csr[s0 + k];            // broadcast load
        float nrm = g_dinv[s] * di;
        if (act) acc += nrm * g_t[s * CC + lane];
    }
    if (act) acc += di * di * g_t[node * CC + lane] + b2[lane];

    const float NEG_INF = __int_as_float(0xff800000u);
    float m = act ? acc : NEG_INF;
#pragma unroll
    for (int mk = 8; mk; mk >>= 1) m = fmaxf(m, __shfl_xor_sync(0xffffffffu, m, mk));
    float e = act ? expf(acc - m) : 0.f;
    float s = e;
#pragma unroll
    for (int mk = 8; mk; mk >>= 1) s += __shfl_xor_sync(0xffffffffu, s, mk);
    float lse = m + logf(s);
    if (act) out[node * CC + lane] = acc - lse;
}

// ---------------- launcher ----------------
extern "C" void kernel_launch(void* const* d_in, const int* in_sizes, int n_in,
                              void* d_out, int out_size) {
    const float* x  = (const float*)d_in[0];
    const int*   ei = (const int*)d_in[1];
    const float* W1 = (const float*)d_in[2];
    const float* b1 = (const float*)d_in[3];
    const float* W2 = (const float*)d_in[4];
    const float* b2 = (const float*)d_in[5];
    float* out = (float*)d_out;

    const int* src = ei;
    const int* dst = ei + EE;

    k_zero_deg<<<(NN + 255) / 256, 256>>>();
    k_deg<<<(EE + 255) / 256, 256>>>(dst);
    k_dinv<<<(NN + 255) / 256, 256>>>();
    k_scan1<<<NBLK, SCAN_B>>>();
    k_scan2<<<1, 32>>>();
    k_finalize<<<(NN + 255) / 256, 256>>>();
    k_fill<<<(EE + 255) / 256, 256>>>(src, dst);
    k_gemm1<<<NPAD / 128, 256>>>(x, W1);
    k_agg1_gemm2<<<NN / 8, 256>>>(b1, W2);
    k_agg2_softmax<<<NN / 8, 256>>>(b2, out);
}

// round 5
// speedup vs baseline: 1.1734x; 1.0658x over previous
#include <cuda_runtime.h>
#include <cuda_bf16.h>
#include <mma.h>
#include <math.h>

using namespace nvcuda;

#define NN   100000
#define NPAD 100096                 // 782 * 128, pad for guard-free MMA epilogue
#define EE   1600000
#define FIN  256
#define HH   128
#define CC   10
#define SCAN_B 1024
#define NBLK ((NN + SCAN_B - 1) / SCAN_B)   // 98

#define LDA 40    // 32 + 8 pad (bf16 elems)
#define LDB 136   // 128 + 8 pad
#define A_ELEMS (128 * LDA)
#define B_ELEMS (32 * LDB)
#define STAGE_ELEMS (2 * A_ELEMS + 2 * B_ELEMS)
#define SMEM_BYTES (2 * STAGE_ELEMS * 2)    // 2 stages, 2B per elem = 75776

// ---------------- scratch (no allocs allowed) ----------------
__device__ int   g_deg[NN];
__device__ int   g_local[NN];
__device__ int   g_bsum[NBLK];
__device__ int   g_boff[NBLK];
__device__ int   g_off[NN];
__device__ int   g_cursor[NN];
__device__ float g_dinv[NN];
__device__ int   g_csr[EE];
__device__ float g_h1[(size_t)NPAD * HH];   // 51.25 MB
__device__ float g_t[NN * CC];

// ---------------- degree / normalization ----------------
__global__ void k_zero_deg() {
    int i = blockIdx.x * blockDim.x + threadIdx.x;
    if (i < NN) g_deg[i] = 0;
}

__global__ void k_deg(const int* __restrict__ dst) {
    int e = blockIdx.x * blockDim.x + threadIdx.x;
    if (e < EE) atomicAdd(&g_deg[dst[e]], 1);
}

__global__ void k_dinv() {
    int i = blockIdx.x * blockDim.x + threadIdx.x;
    if (i < NN) g_dinv[i] = rsqrtf((float)(g_deg[i] + 1));  // +1 self loop
}

// ---------------- CSR build: scan + bucket fill ----------------
__global__ void k_scan1() {
    __shared__ int sh[SCAN_B];
    int tid = threadIdx.x;
    int i = blockIdx.x * SCAN_B + tid;
    int v = (i < NN) ? g_deg[i] : 0;
    sh[tid] = v;
    __syncthreads();
    for (int ofs = 1; ofs < SCAN_B; ofs <<= 1) {
        int t = (tid >= ofs) ? sh[tid - ofs] : 0;
        __syncthreads();
        sh[tid] += t;
        __syncthreads();
    }
    if (i < NN) g_local[i] = sh[tid] - v;     // exclusive
    if (tid == SCAN_B - 1) g_bsum[blockIdx.x] = sh[tid];
}

__global__ void k_scan2() {
    if (threadIdx.x == 0 && blockIdx.x == 0) {
        int acc = 0;
        for (int b = 0; b < NBLK; b++) { g_boff[b] = acc; acc += g_bsum[b]; }
    }
}

__global__ void k_finalize() {
    int i = blockIdx.x * blockDim.x + threadIdx.x;
    if (i < NN) {
        int o = g_local[i] + g_boff[i >> 10];
        g_off[i] = o;
        g_cursor[i] = o;
    }
}

__global__ void k_fill(const int* __restrict__ src, const int* __restrict__ dst) {
    int e = blockIdx.x * blockDim.x + threadIdx.x;
    if (e < EE) {
        int d = dst[e];
        int pos = atomicAdd(&g_cursor[d], 1);
        g_csr[pos] = src[e];
    }
}

// ---------------- GEMM1: h1 = x @ W1, bf16x3 split, double-buffered ----------------
__device__ __forceinline__ void split2(float v, __nv_bfloat16& h, __nv_bfloat16& l) {
    h = __float2bfloat16(v);
    l = __float2bfloat16(v - __bfloat162float(h));
}

__global__ void __launch_bounds__(256) k_gemm1(const float* __restrict__ x,
                                               const float* __restrict__ W1) {
    extern __shared__ __nv_bfloat16 sm[];
    int tid = threadIdx.x;
    int wid = tid >> 5;
    int wm = wid >> 1;        // 0..3
    int wn = wid & 1;         // 0..1
    int row0 = blockIdx.x * 128;

    // per-thread load coordinates (fixed across k-steps)
    int af4  = tid;                    // handles af4 + r*256
    int arow[4], ac4[4], agr[4], brow[4], bc4[4];
#pragma unroll
    for (int r = 0; r < 4; r++) {
        int f4 = af4 + r * 256;
        arow[r] = f4 >> 3;  ac4[r] = (f4 & 7) * 4;
        int gr = row0 + arow[r]; if (gr >= NN) gr = NN - 1;
        agr[r] = gr;
        brow[r] = f4 >> 5;  bc4[r] = (f4 & 31) * 4;
    }

    wmma::fragment<wmma::accumulator, 16, 16, 16, float> c[2][4];
#pragma unroll
    for (int i = 0; i < 2; i++)
#pragma unroll
        for (int j = 0; j < 4; j++) wmma::fill_fragment(c[i][j], 0.f);

    float4 pa[4], pb[4];

    auto load_regs = [&](int t) {
#pragma unroll
        for (int r = 0; r < 4; r++)
            pa[r] = *reinterpret_cast<const float4*>(&x[(size_t)agr[r] * FIN + t * 32 + ac4[r]]);
#pragma unroll
        for (int r = 0; r < 4; r++)
            pb[r] = *reinterpret_cast<const float4*>(&W1[(size_t)(t * 32 + brow[r]) * HH + bc4[r]]);
    };
    auto store_smem = [&](int buf) {
        __nv_bfloat16* Ah = sm + buf * STAGE_ELEMS;
        __nv_bfloat16* Al = Ah + A_ELEMS;
        __nv_bfloat16* Bh = Al + A_ELEMS;
        __nv_bfloat16* Bl = Bh + B_ELEMS;
#pragma unroll
        for (int r = 0; r < 4; r++) {
            __nv_bfloat16 h, l;
            int o = arow[r] * LDA + ac4[r];
            split2(pa[r].x, h, l); Ah[o+0] = h; Al[o+0] = l;
            split2(pa[r].y, h, l); Ah[o+1] = h; Al[o+1] = l;
            split2(pa[r].z, h, l); Ah[o+2] = h; Al[o+2] = l;
            split2(pa[r].w, h, l); Ah[o+3] = h; Al[o+3] = l;
        }
#pragma unroll
        for (int r = 0; r < 4; r++) {
            __nv_bfloat16 h, l;
            int o = brow[r] * LDB + bc4[r];
            split2(pb[r].x, h, l); Bh[o+0] = h; Bl[o+0] = l;
            split2(pb[r].y, h, l); Bh[o+1] = h; Bl[o+1] = l;
            split2(pb[r].z, h, l); Bh[o+2] = h; Bl[o+2] = l;
            split2(pb[r].w, h, l); Bh[o+3] = h; Bl[o+3] = l;
        }
    };
    auto do_mma = [&](int buf) {
        __nv_bfloat16* Ah = sm + buf * STAGE_ELEMS;
        __nv_bfloat16* Al = Ah + A_ELEMS;
        __nv_bfloat16* Bh = Al + A_ELEMS;
        __nv_bfloat16* Bl = Bh + B_ELEMS;
#pragma unroll
        for (int kk = 0; kk < 32; kk += 16) {
            wmma::fragment<wmma::matrix_a, 16, 16, 16, __nv_bfloat16, wmma::row_major> ah[2], al[2];
            wmma::fragment<wmma::matrix_b, 16, 16, 16, __nv_bfloat16, wmma::row_major> bh[4], bl[4];
#pragma unroll
            for (int i = 0; i < 2; i++) {
                wmma::load_matrix_sync(ah[i], &Ah[(wm*32 + i*16)*LDA + kk], LDA);
                wmma::load_matrix_sync(al[i], &Al[(wm*32 + i*16)*LDA + kk], LDA);
            }
#pragma unroll
            for (int j = 0; j < 4; j++) {
                wmma::load_matrix_sync(bh[j], &Bh[kk*LDB + wn*64 + j*16], LDB);
                wmma::load_matrix_sync(bl[j], &Bl[kk*LDB + wn*64 + j*16], LDB);
            }
#pragma unroll
            for (int i = 0; i < 2; i++)
#pragma unroll
                for (int j = 0; j < 4; j++) {
                    wmma::mma_sync(c[i][j], ah[i], bh[j], c[i][j]);
                    wmma::mma_sync(c[i][j], ah[i], bl[j], c[i][j]);
                    wmma::mma_sync(c[i][j], al[i], bh[j], c[i][j]);
                }
        }
    };

    // prologue
    load_regs(0);
    store_smem(0);
    __syncthreads();

    const int NT = FIN / 32;   // 8 k-steps
    for (int t = 0; t < NT; t++) {
        if (t + 1 < NT) load_regs(t + 1);    // global loads in flight during MMA
        do_mma(t & 1);
        if (t + 1 < NT) {
            __syncthreads();                  // all warps done reading before refill
            store_smem((t + 1) & 1);
            __syncthreads();
        }
    }

#pragma unroll
    for (int i = 0; i < 2; i++)
#pragma unroll
        for (int j = 0; j < 4; j++)
            wmma::store_matrix_sync(
                &g_h1[(size_t)(row0 + wm*32 + i*16) * HH + wn*64 + j*16],
                c[i][j], HH, wmma::mem_row_major);
}

// ---------------- fused: agg1 (gather) + b1 + relu + GEMM2 -> t ----------------
__global__ void k_agg1_gemm2(const float* __restrict__ b1, const float* __restrict__ W2) {
    __shared__ float sW2[CC][HH];   // transposed: [c][j]
    int tid = threadIdx.x;
    for (int i = tid; i < HH * CC; i += blockDim.x) {
        int j = i / CC, c = i % CC;
        sW2[c][j] = W2[i];
    }
    __syncthreads();

    int lane = tid & 31;
    int node = blockIdx.x * 8 + (tid >> 5);

    float di = g_dinv[node];
    int s0 = g_off[node];
    int cnt = g_deg[node];
    const float4* h1v = reinterpret_cast<const float4*>(g_h1);

    float4 a0 = make_float4(0.f, 0.f, 0.f, 0.f);
    float4 a1 = make_float4(0.f, 0.f, 0.f, 0.f);
    int k = 0;
    for (; k + 2 <= cnt; k += 2) {          // two gathers in flight
        int sA = g_csr[s0 + k];
        int sB = g_csr[s0 + k + 1];
        float nA = g_dinv[sA] * di;
        float nB = g_dinv[sB] * di;
        float4 vA = h1v[sA * (HH / 4) + lane];
        float4 vB = h1v[sB * (HH / 4) + lane];
        a0.x += vA.x * nA; a0.y += vA.y * nA; a0.z += vA.z * nA; a0.w += vA.w * nA;
        a1.x += vB.x * nB; a1.y += vB.y * nB; a1.z += vB.z * nB; a1.w += vB.w * nB;
    }
    if (k < cnt) {
        int s = g_csr[s0 + k];
        float nrm = g_dinv[s] * di;
        float4 v = h1v[s * (HH / 4) + lane];
        a0.x += v.x * nrm; a0.y += v.y * nrm; a0.z += v.z * nrm; a0.w += v.w * nrm;
    }
    {   // self loop
        float nrm = di * di;
        float4 v = h1v[node * (HH / 4) + lane];
        a1.x += v.x * nrm; a1.y += v.y * nrm; a1.z += v.z * nrm; a1.w += v.w * nrm;
    }
    float4 acc = make_float4(a0.x + a1.x, a0.y + a1.y, a0.z + a1.z, a0.w + a1.w);

    float4 bb = reinterpret_cast<const float4*>(b1)[lane];
    float h0  = fmaxf(acc.x + bb.x, 0.f);
    float h1r = fmaxf(acc.y + bb.y, 0.f);
    float h2r = fmaxf(acc.z + bb.z, 0.f);
    float h3r = fmaxf(acc.w + bb.w, 0.f);

    float myval = 0.f;
#pragma unroll
    for (int c = 0; c < CC; c++) {
        float4 w = reinterpret_cast<float4*>(&sW2[c][0])[lane];
        float p = h0 * w.x + h1r * w.y + h2r * w.z + h3r * w.w;
#pragma unroll
        for (int m = 16; m; m >>= 1) p += __shfl_xor_sync(0xffffffffu, p, m);
        if (lane == c) myval = p;
    }
    if (lane < CC) g_t[node * CC + lane] = myval;
}

// ---------------- fused: agg2 (gather) + b2 + log_softmax -> out ----------------
__global__ void k_agg2_softmax(const float* __restrict__ b2, float* __restrict__ out) {
    int tid = threadIdx.x;
    int lane = tid & 31;
    int node = blockIdx.x * 8 + (tid >> 5);

    float di = g_dinv[node];
    int s0 = g_off[node];
    int cnt = g_deg[node];
    bool act = lane < CC;

    float acc = 0.f;
    for (int k = 0; k < cnt; k++) {
        int s = g_csr[s0 + k];            // broadcast load
        float nrm = g_dinv[s] * di;
        if (act) acc += nrm * g_t[s * CC + lane];
    }
    if (act) acc += di * di * g_t[node * CC + lane] + b2[lane];

    const float NEG_INF = __int_as_float(0xff800000u);
    float m = act ? acc : NEG_INF;
#pragma unroll
    for (int mk = 8; mk; mk >>= 1) m = fmaxf(m, __shfl_xor_sync(0xffffffffu, m, mk));
    float e = act ? expf(acc - m) : 0.f;
    float s = e;
#pragma unroll
    for (int mk = 8; mk; mk >>= 1) s += __shfl_xor_sync(0xffffffffu, s, mk);
    float lse = m + logf(s);
    if (act) out[node * CC + lane] = acc - lse;
}

// ---------------- launcher ----------------
extern "C" void kernel_launch(void* const* d_in, const int* in_sizes, int n_in,
                              void* d_out, int out_size) {
    const float* x  = (const float*)d_in[0];
    const int*   ei = (const int*)d_in[1];
    const float* W1 = (const float*)d_in[2];
    const float* b1 = (const float*)d_in[3];
    const float* W2 = (const float*)d_in[4];
    const float* b2 = (const float*)d_in[5];
    float* out = (float*)d_out;

    const int* src = ei;
    const int* dst = ei + EE;

    cudaFuncSetAttribute(k_gemm1, cudaFuncAttributeMaxDynamicSharedMemorySize, SMEM_BYTES);

    // k_gemm1 placed at launch slot #4 so the fixed ncu capture window
    // (which profiled launch #4 = k_scan1 in prior rounds) lands on it.
    k_zero_deg<<<(NN + 255) / 256, 256>>>();
    k_deg<<<(EE + 255) / 256, 256>>>(dst);
    k_dinv<<<(NN + 255) / 256, 256>>>();
    k_gemm1<<<NPAD / 128, 256, SMEM_BYTES>>>(x, W1);
    k_scan1<<<NBLK, SCAN_B>>>();
    k_scan2<<<1, 32>>>();
    k_finalize<<<(NN + 255) / 256, 256>>>();
    k_fill<<<(EE + 255) / 256, 256>>>(src, dst);
    k_agg1_gemm2<<<NN / 8, 256>>>(b1, W2);
    k_agg2_softmax<<<NN / 8, 256>>>(b2, out);
}

// round 6
// speedup vs baseline: 1.2130x; 1.0338x over previous
#include <cuda_runtime.h>
#include <cuda_bf16.h>
#include <mma.h>
#include <math.h>

using namespace nvcuda;

#define NN   100000
#define NPAD 100096                 // 1564 * 64, pad for guard-free MMA epilogue
#define EE   1600000
#define FIN  256
#define HH   128
#define CC   10
#define SCAN_B 1024
#define NBLK ((NN + SCAN_B - 1) / SCAN_B)   // 98

#define LDA 40    // 32 + 8 pad (bf16 elems)
#define LDB 136   // 128 + 8 pad
#define A_ELEMS (64 * LDA)                   // 2560
#define B_ELEMS (32 * LDB)                   // 4352
#define STAGE_ELEMS (2 * A_ELEMS + 2 * B_ELEMS)   // 13824
#define SMEM_BYTES (2 * STAGE_ELEMS * 2)          // 55296 B

// ---------------- scratch (no allocs allowed) ----------------
__device__ int   g_deg[NN];
__device__ int   g_local[NN];
__device__ int   g_bsum[NBLK];
__device__ int   g_boff[NBLK];
__device__ int   g_off[NN];
__device__ int   g_cursor[NN];
__device__ float g_dinv[NN];
__device__ int   g_csr[EE];
__device__ float g_h1[(size_t)NPAD * HH];   // 51.25 MB
__device__ float g_t[NN * CC];

// ---------------- degree / normalization ----------------
__global__ void k_zero_deg() {
    int i = blockIdx.x * blockDim.x + threadIdx.x;
    if (i < NN) g_deg[i] = 0;
}

__global__ void k_deg(const int* __restrict__ dst) {
    int e = blockIdx.x * blockDim.x + threadIdx.x;
    if (e < EE) atomicAdd(&g_deg[dst[e]], 1);
}

__global__ void k_dinv() {
    int i = blockIdx.x * blockDim.x + threadIdx.x;
    if (i < NN) g_dinv[i] = rsqrtf((float)(g_deg[i] + 1));  // +1 self loop
}

// ---------------- CSR build: scan + bucket fill ----------------
__global__ void k_scan1() {
    __shared__ int sh[SCAN_B];
    int tid = threadIdx.x;
    int i = blockIdx.x * SCAN_B + tid;
    int v = (i < NN) ? g_deg[i] : 0;
    sh[tid] = v;
    __syncthreads();
    for (int ofs = 1; ofs < SCAN_B; ofs <<= 1) {
        int t = (tid >= ofs) ? sh[tid - ofs] : 0;
        __syncthreads();
        sh[tid] += t;
        __syncthreads();
    }
    if (i < NN) g_local[i] = sh[tid] - v;     // exclusive
    if (tid == SCAN_B - 1) g_bsum[blockIdx.x] = sh[tid];
}

__global__ void k_scan2() {
    if (threadIdx.x == 0 && blockIdx.x == 0) {
        int acc = 0;
        for (int b = 0; b < NBLK; b++) { g_boff[b] = acc; acc += g_bsum[b]; }
    }
}

__global__ void k_finalize() {
    int i = blockIdx.x * blockDim.x + threadIdx.x;
    if (i < NN) {
        int o = g_local[i] + g_boff[i >> 10];
        g_off[i] = o;
        g_cursor[i] = o;
    }
}

__global__ void k_fill(const int* __restrict__ src, const int* __restrict__ dst) {
    int e = blockIdx.x * blockDim.x + threadIdx.x;
    if (e < EE) {
        int d = dst[e];
        int pos = atomicAdd(&g_cursor[d], 1);
        g_csr[pos] = src[e];
    }
}

// ---------------- GEMM1: h1 = x @ W1, bf16x3 split, double-buffered ----------------
// BM=64, BN=128, BK=32; 256 thr = 8 warps (2m x 4n); warp tile 32x32.
// Sized so 2 CTAs fit per SM (smem 55.3KB, regs <=128 via launch_bounds).
__device__ __forceinline__ void split2(float v, __nv_bfloat16& h, __nv_bfloat16& l) {
    h = __float2bfloat16(v);
    l = __float2bfloat16(v - __bfloat162float(h));
}

__global__ void __launch_bounds__(256, 2) k_gemm1(const float* __restrict__ x,
                                                  const float* __restrict__ W1) {
    extern __shared__ __nv_bfloat16 sm[];
    int tid = threadIdx.x;
    int wid = tid >> 5;
    int wm = wid & 1;         // 0..1  (m)
    int wn = wid >> 1;        // 0..3  (n)
    int row0 = blockIdx.x * 64;

    // per-thread load coordinates (fixed across k-steps)
    int arow[2], ac4[2], agr[2], brow[4], bc4[4];
#pragma unroll
    for (int r = 0; r < 2; r++) {
        int f4 = tid + r * 256;         // 0..511
        arow[r] = f4 >> 3;  ac4[r] = (f4 & 7) * 4;
        int gr = row0 + arow[r]; if (gr >= NN) gr = NN - 1;
        agr[r] = gr;
    }
#pragma unroll
    for (int r = 0; r < 4; r++) {
        int f4 = tid + r * 256;         // 0..1023
        brow[r] = f4 >> 5;  bc4[r] = (f4 & 31) * 4;
    }

    wmma::fragment<wmma::accumulator, 16, 16, 16, float> c[2][2];
#pragma unroll
    for (int i = 0; i < 2; i++)
#pragma unroll
        for (int j = 0; j < 2; j++) wmma::fill_fragment(c[i][j], 0.f);

    float4 pa[2], pb[4];

    auto load_regs = [&](int t) {
#pragma unroll
        for (int r = 0; r < 2; r++)
            pa[r] = *reinterpret_cast<const float4*>(&x[(size_t)agr[r] * FIN + t * 32 + ac4[r]]);
#pragma unroll
        for (int r = 0; r < 4; r++)
            pb[r] = *reinterpret_cast<const float4*>(&W1[(size_t)(t * 32 + brow[r]) * HH + bc4[r]]);
    };
    auto store_smem = [&](int buf) {
        __nv_bfloat16* Ah = sm + buf * STAGE_ELEMS;
        __nv_bfloat16* Al = Ah + A_ELEMS;
        __nv_bfloat16* Bh = Al + A_ELEMS;
        __nv_bfloat16* Bl = Bh + B_ELEMS;
#pragma unroll
        for (int r = 0; r < 2; r++) {
            __nv_bfloat16 h, l;
            int o = arow[r] * LDA + ac4[r];
            split2(pa[r].x, h, l); Ah[o+0] = h; Al[o+0] = l;
            split2(pa[r].y, h, l); Ah[o+1] = h; Al[o+1] = l;
            split2(pa[r].z, h, l); Ah[o+2] = h; Al[o+2] = l;
            split2(pa[r].w, h, l); Ah[o+3] = h; Al[o+3] = l;
        }
#pragma unroll
        for (int r = 0; r < 4; r++) {
            __nv_bfloat16 h, l;
            int o = brow[r] * LDB + bc4[r];
            split2(pb[r].x, h, l); Bh[o+0] = h; Bl[o+0] = l;
            split2(pb[r].y, h, l); Bh[o+1] = h; Bl[o+1] = l;
            split2(pb[r].z, h, l); Bh[o+2] = h; Bl[o+2] = l;
            split2(pb[r].w, h, l); Bh[o+3] = h; Bl[o+3] = l;
        }
    };
    auto do_mma = [&](int buf) {
        __nv_bfloat16* Ah = sm + buf * STAGE_ELEMS;
        __nv_bfloat16* Al = Ah + A_ELEMS;
        __nv_bfloat16* Bh = Al + A_ELEMS;
        __nv_bfloat16* Bl = Bh + B_ELEMS;
#pragma unroll
        for (int kk = 0; kk < 32; kk += 16) {
            wmma::fragment<wmma::matrix_a, 16, 16, 16, __nv_bfloat16, wmma::row_major> ah[2], al[2];
            wmma::fragment<wmma::matrix_b, 16, 16, 16, __nv_bfloat16, wmma::row_major> bh[2], bl[2];
#pragma unroll
            for (int i = 0; i < 2; i++) {
                wmma::load_matrix_sync(ah[i], &Ah[(wm*32 + i*16)*LDA + kk], LDA);
                wmma::load_matrix_sync(al[i], &Al[(wm*32 + i*16)*LDA + kk], LDA);
            }
#pragma unroll
            for (int j = 0; j < 2; j++) {
                wmma::load_matrix_sync(bh[j], &Bh[kk*LDB + wn*32 + j*16], LDB);
                wmma::load_matrix_sync(bl[j], &Bl[kk*LDB + wn*32 + j*16], LDB);
            }
#pragma unroll
            for (int i = 0; i < 2; i++)
#pragma unroll
                for (int j = 0; j < 2; j++) {
                    wmma::mma_sync(c[i][j], ah[i], bh[j], c[i][j]);
                    wmma::mma_sync(c[i][j], ah[i], bl[j], c[i][j]);
                    wmma::mma_sync(c[i][j], al[i], bh[j], c[i][j]);
                }
        }
    };

    // prologue
    load_regs(0);
    store_smem(0);
    __syncthreads();

    const int NT = FIN / 32;   // 8 k-steps
    for (int t = 0; t < NT; t++) {
        if (t + 1 < NT) load_regs(t + 1);    // global loads in flight during MMA
        do_mma(t & 1);
        if (t + 1 < NT) {
            __syncthreads();
            store_smem((t + 1) & 1);
            __syncthreads();
        }
    }

#pragma unroll
    for (int i = 0; i < 2; i++)
#pragma unroll
        for (int j = 0; j < 2; j++)
            wmma::store_matrix_sync(
                &g_h1[(size_t)(row0 + wm*32 + i*16) * HH + wn*32 + j*16],
                c[i][j], HH, wmma::mem_row_major);
}

// ---------------- fused: agg1 (gather) + b1 + relu + GEMM2 -> t ----------------
__global__ void k_agg1_gemm2(const float* __restrict__ b1, const float* __restrict__ W2) {
    __shared__ float sW2[CC][HH];   // transposed: [c][j]
    int tid = threadIdx.x;
    for (int i = tid; i < HH * CC; i += blockDim.x) {
        int j = i / CC, c = i % CC;
        sW2[c][j] = W2[i];
    }
    __syncthreads();

    int lane = tid & 31;
    int node = blockIdx.x * 8 + (tid >> 5);

    float di = g_dinv[node];
    int s0 = g_off[node];
    int cnt = g_deg[node];
    const float4* h1v = reinterpret_cast<const float4*>(g_h1);

    float4 a0 = make_float4(0.f, 0.f, 0.f, 0.f);
    float4 a1 = make_float4(0.f, 0.f, 0.f, 0.f);
    float4 a2 = make_float4(0.f, 0.f, 0.f, 0.f);
    float4 a3 = make_float4(0.f, 0.f, 0.f, 0.f);
    int k = 0;
    for (; k + 4 <= cnt; k += 4) {          // four gathers in flight
        int sA = g_csr[s0 + k];
        int sB = g_csr[s0 + k + 1];
        int sC = g_csr[s0 + k + 2];
        int sD = g_csr[s0 + k + 3];
        float nA = g_dinv[sA] * di;
        float nB = g_dinv[sB] * di;
        float nC = g_dinv[sC] * di;
        float nD = g_dinv[sD] * di;
        float4 vA = h1v[sA * (HH / 4) + lane];
        float4 vB = h1v[sB * (HH / 4) + lane];
        float4 vC = h1v[sC * (HH / 4) + lane];
        float4 vD = h1v[sD * (HH / 4) + lane];
        a0.x += vA.x * nA; a0.y += vA.y * nA; a0.z += vA.z * nA; a0.w += vA.w * nA;
        a1.x += vB.x * nB; a1.y += vB.y * nB; a1.z += vB.z * nB; a1.w += vB.w * nB;
        a2.x += vC.x * nC; a2.y += vC.y * nC; a2.z += vC.z * nC; a2.w += vC.w * nC;
        a3.x += vD.x * nD; a3.y += vD.y * nD; a3.z += vD.z * nD; a3.w += vD.w * nD;
    }
    for (; k < cnt; k++) {
        int s = g_csr[s0 + k];
        float nrm = g_dinv[s] * di;
        float4 v = h1v[s * (HH / 4) + lane];
        a0.x += v.x * nrm; a0.y += v.y * nrm; a0.z += v.z * nrm; a0.w += v.w * nrm;
    }
    {   // self loop
        float nrm = di * di;
        float4 v = h1v[node * (HH / 4) + lane];
        a1.x += v.x * nrm; a1.y += v.y * nrm; a1.z += v.z * nrm; a1.w += v.w * nrm;
    }
    float4 acc = make_float4(a0.x + a1.x + a2.x + a3.x,
                             a0.y + a1.y + a2.y + a3.y,
                             a0.z + a1.z + a2.z + a3.z,
                             a0.w + a1.w + a2.w + a3.w);

    float4 bb = reinterpret_cast<const float4*>(b1)[lane];
    float h0  = fmaxf(acc.x + bb.x, 0.f);
    float h1r = fmaxf(acc.y + bb.y, 0.f);
    float h2r = fmaxf(acc.z + bb.z, 0.f);
    float h3r = fmaxf(acc.w + bb.w, 0.f);

    float myval = 0.f;
#pragma unroll
    for (int c = 0; c < CC; c++) {
        float4 w = reinterpret_cast<float4*>(&sW2[c][0])[lane];
        float p = h0 * w.x + h1r * w.y + h2r * w.z + h3r * w.w;
#pragma unroll
        for (int m = 16; m; m >>= 1) p += __shfl_xor_sync(0xffffffffu, p, m);
        if (lane == c) myval = p;
    }
    if (lane < CC) g_t[node * CC + lane] = myval;
}

// ---------------- fused: agg2 (gather) + b2 + log_softmax -> out ----------------
__global__ void k_agg2_softmax(const float* __restrict__ b2, float* __restrict__ out) {
    int tid = threadIdx.x;
    int lane = tid & 31;
    int node = blockIdx.x * 8 + (tid >> 5);

    float di = g_dinv[node];
    int s0 = g_off[node];
    int cnt = g_deg[node];
    bool act = lane < CC;

    float acc = 0.f;
    for (int k = 0; k < cnt; k++) {
        int s = g_csr[s0 + k];            // broadcast load
        float nrm = g_dinv[s] * di;
        if (act) acc += nrm * g_t[s * CC + lane];
    }
    if (act) acc += di * di * g_t[node * CC + lane] + b2[lane];

    const float NEG_INF = __int_as_float(0xff800000u);
    float m = act ? acc : NEG_INF;
#pragma unroll
    for (int mk = 8; mk; mk >>= 1) m = fmaxf(m, __shfl_xor_sync(0xffffffffu, m, mk));
    float e = act ? expf(acc - m) : 0.f;
    float s = e;
#pragma unroll
    for (int mk = 8; mk; mk >>= 1) s += __shfl_xor_sync(0xffffffffu, s, mk);
    float lse = m + logf(s);
    if (act) out[node * CC + lane] = acc - lse;
}

// ---------------- launcher ----------------
extern "C" void kernel_launch(void* const* d_in, const int* in_sizes, int n_in,
                              void* d_out, int out_size) {
    const float* x  = (const float*)d_in[0];
    const int*   ei = (const int*)d_in[1];
    const float* W1 = (const float*)d_in[2];
    const float* b1 = (const float*)d_in[3];
    const float* W2 = (const float*)d_in[4];
    const float* b2 = (const float*)d_in[5];
    float* out = (float*)d_out;

    const int* src = ei;
    const int* dst = ei + EE;

    cudaFuncSetAttribute(k_gemm1, cudaFuncAttributeMaxDynamicSharedMemorySize, SMEM_BYTES);

    // k_gemm1 stays at launch slot #4 (the profiled slot in prior rounds).
    k_zero_deg<<<(NN + 255) / 256, 256>>>();
    k_deg<<<(EE + 255) / 256, 256>>>(dst);
    k_dinv<<<(NN + 255) / 256, 256>>>();
    k_gemm1<<<NPAD / 64, 256, SMEM_BYTES>>>(x, W1);
    k_scan1<<<NBLK, SCAN_B>>>();
    k_scan2<<<1, 32>>>();
    k_finalize<<<(NN + 255) / 256, 256>>>();
    k_fill<<<(EE + 255) / 256, 256>>>(src, dst);
    k_agg1_gemm2<<<NN / 8, 256>>>(b1, W2);
    k_agg2_softmax<<<NN / 8, 256>>>(b2, out);
}

// round 9
// speedup vs baseline: 1.2902x; 1.0636x over previous
#include <cuda_runtime.h>
#include <cuda_bf16.h>
#include <cuda_fp16.h>
#include <mma.h>
#include <math.h>
#include <stdint.h>

using namespace nvcuda;

#define NN   100000
#define NPAD 100096                 // 1564 * 64
#define EE   1600000
#define FIN  256
#define HH   128
#define CC   10
#define SCAN_B 1024
#define NBLK ((NN + SCAN_B - 1) / SCAN_B)   // 98

#define LDA 40    // 32 + 8 pad (bf16 elems)
#define LDB 136   // 128 + 8 pad
#define A_ELEMS (64 * LDA)                   // 2560
#define B_ELEMS (32 * LDB)                   // 4352
#define STAGE_ELEMS (2 * A_ELEMS + 2 * B_ELEMS)   // 13824
#define SMEM_BYTES (2 * STAGE_ELEMS * 2)          // 55296 B (also covers 32KB C-staging)

// ---------------- scratch (no allocs allowed) ----------------
__device__ int    g_deg[NN];
__device__ int    g_local[NN];
__device__ int    g_bsum[NBLK];
__device__ int    g_boff[NBLK];
__device__ int    g_off[NN];
__device__ int    g_cursor[NN];
__device__ float  g_dinv[NN];
__device__ int    g_csr[EE];
__device__ __half g_h1[(size_t)NPAD * HH];   // 25.6 MB, L2-resident
__device__ float  g_t[NN * CC];

// ---------------- degree ----------------
__global__ void k_zero_deg() {
    int i = blockIdx.x * blockDim.x + threadIdx.x;
    if (i < NN) g_deg[i] = 0;
}
__global__ void k_deg(const int* __restrict__ dst) {
    int e = blockIdx.x * blockDim.x + threadIdx.x;
    if (e < EE) atomicAdd(&g_deg[dst[e]], 1);
}

// ---------------- CSR build ----------------
__global__ void k_scan1() {
    __shared__ int sh[SCAN_B];
    int tid = threadIdx.x;
    int i = blockIdx.x * SCAN_B + tid;
    int v = (i < NN) ? g_deg[i] : 0;
    sh[tid] = v;
    __syncthreads();
    for (int ofs = 1; ofs < SCAN_B; ofs <<= 1) {
        int t = (tid >= ofs) ? sh[tid - ofs] : 0;
        __syncthreads();
        sh[tid] += t;
        __syncthreads();
    }
    if (i < NN) g_local[i] = sh[tid] - v;
    if (tid == SCAN_B - 1) g_bsum[blockIdx.x] = sh[tid];
}
__global__ void k_scan2() {
    __shared__ int sh[128];
    int t = threadIdx.x;
    int v = (t < NBLK) ? g_bsum[t] : 0;
    sh[t] = v;
    __syncthreads();
    for (int o = 1; o < 128; o <<= 1) {
        int x = (t >= o) ? sh[t - o] : 0;
        __syncthreads();
        sh[t] += x;
        __syncthreads();
    }
    if (t < NBLK) g_boff[t] = sh[t] - v;   // exclusive block offsets
}
__global__ void k_finalize() {
    int i = blockIdx.x * blockDim.x + threadIdx.x;
    if (i < NN) {
        int o = g_local[i] + g_boff[i >> 10];
        g_off[i] = o;
        g_cursor[i] = o;
        g_dinv[i] = rsqrtf((float)(g_deg[i] + 1));   // +1 self loop
    }
}
__global__ void k_fill(const int* __restrict__ src, const int* __restrict__ dst) {
    int e = blockIdx.x * blockDim.x + threadIdx.x;
    if (e < EE) {
        int d = dst[e];
        int pos = atomicAdd(&g_cursor[d], 1);
        g_csr[pos] = src[e];
    }
}

// ---------------- GEMM1: h1 = x @ W1, bf16x3 split, double-buffered, fp16 out ----------------
__device__ __forceinline__ void split2(float v, __nv_bfloat16& h, __nv_bfloat16& l) {
    h = __float2bfloat16(v);
    l = __float2bfloat16(v - __bfloat162float(h));
}

__global__ void __launch_bounds__(256, 2) k_gemm1(const float* __restrict__ x,
                                                  const float* __restrict__ W1) {
    extern __shared__ __nv_bfloat16 sm[];
    int tid = threadIdx.x;
    int wid = tid >> 5;
    int wm = wid & 1;         // 0..1  (m)
    int wn = wid >> 1;        // 0..3  (n)
    int row0 = blockIdx.x * 64;

    int arow[2], ac4[2], agr[2], brow[4], bc4[4];
#pragma unroll
    for (int r = 0; r < 2; r++) {
        int f4 = tid + r * 256;
        arow[r] = f4 >> 3;  ac4[r] = (f4 & 7) * 4;
        int gr = row0 + arow[r]; if (gr >= NN) gr = NN - 1;
        agr[r] = gr;
    }
#pragma unroll
    for (int r = 0; r < 4; r++) {
        int f4 = tid + r * 256;
        brow[r] = f4 >> 5;  bc4[r] = (f4 & 31) * 4;
    }

    wmma::fragment<wmma::accumulator, 16, 16, 16, float> c[2][2];
#pragma unroll
    for (int i = 0; i < 2; i++)
#pragma unroll
        for (int j = 0; j < 2; j++) wmma::fill_fragment(c[i][j], 0.f);

    float4 pa[2], pb[4];

    auto load_regs = [&](int t) {
#pragma unroll
        for (int r = 0; r < 2; r++)
            pa[r] = *reinterpret_cast<const float4*>(&x[(size_t)agr[r] * FIN + t * 32 + ac4[r]]);
#pragma unroll
        for (int r = 0; r < 4; r++)
            pb[r] = *reinterpret_cast<const float4*>(&W1[(size_t)(t * 32 + brow[r]) * HH + bc4[r]]);
    };
    auto store_smem = [&](int buf) {
        __nv_bfloat16* Ah = sm + buf * STAGE_ELEMS;
        __nv_bfloat16* Al = Ah + A_ELEMS;
        __nv_bfloat16* Bh = Al + A_ELEMS;
        __nv_bfloat16* Bl = Bh + B_ELEMS;
#pragma unroll
        for (int r = 0; r < 2; r++) {
            __nv_bfloat16 h, l;
            int o = arow[r] * LDA + ac4[r];
            split2(pa[r].x, h, l); Ah[o+0] = h; Al[o+0] = l;
            split2(pa[r].y, h, l); Ah[o+1] = h; Al[o+1] = l;
            split2(pa[r].z, h, l); Ah[o+2] = h; Al[o+2] = l;
            split2(pa[r].w, h, l); Ah[o+3] = h; Al[o+3] = l;
        }
#pragma unroll
        for (int r = 0; r < 4; r++) {
            __nv_bfloat16 h, l;
            int o = brow[r] * LDB + bc4[r];
            split2(pb[r].x, h, l); Bh[o+0] = h; Bl[o+0] = l;
            split2(pb[r].y, h, l); Bh[o+1] = h; Bl[o+1] = l;
            split2(pb[r].z, h, l); Bh[o+2] = h; Bl[o+2] = l;
            split2(pb[r].w, h, l); Bh[o+3] = h; Bl[o+3] = l;
        }
    };
    auto do_mma = [&](int buf) {
        __nv_bfloat16* Ah = sm + buf * STAGE_ELEMS;
        __nv_bfloat16* Al = Ah + A_ELEMS;
        __nv_bfloat16* Bh = Al + A_ELEMS;
        __nv_bfloat16* Bl = Bh + B_ELEMS;
#pragma unroll
        for (int kk = 0; kk < 32; kk += 16) {
            wmma::fragment<wmma::matrix_a, 16, 16, 16, __nv_bfloat16, wmma::row_major> ah[2], al[2];
            wmma::fragment<wmma::matrix_b, 16, 16, 16, __nv_bfloat16, wmma::row_major> bh[2], bl[2];
#pragma unroll
            for (int i = 0; i < 2; i++) {
                wmma::load_matrix_sync(ah[i], &Ah[(wm*32 + i*16)*LDA + kk], LDA);
                wmma::load_matrix_sync(al[i], &Al[(wm*32 + i*16)*LDA + kk], LDA);
            }
#pragma unroll
            for (int j = 0; j < 2; j++) {
                wmma::load_matrix_sync(bh[j], &Bh[kk*LDB + wn*32 + j*16], LDB);
                wmma::load_matrix_sync(bl[j], &Bl[kk*LDB + wn*32 + j*16], LDB);
            }
#pragma unroll
            for (int i = 0; i < 2; i++)
#pragma unroll
                for (int j = 0; j < 2; j++) {
                    wmma::mma_sync(c[i][j], ah[i], bh[j], c[i][j]);
                    wmma::mma_sync(c[i][j], ah[i], bl[j], c[i][j]);
                    wmma::mma_sync(c[i][j], al[i], bh[j], c[i][j]);
                }
        }
    };

    load_regs(0);
    store_smem(0);
    __syncthreads();

    const int NT = FIN / 32;   // 8 k-steps
    for (int t = 0; t < NT; t++) {
        if (t + 1 < NT) load_regs(t + 1);
        do_mma(t & 1);
        if (t + 1 < NT) {
            __syncthreads();
            store_smem((t + 1) & 1);
            __syncthreads();
        }
    }

    // epilogue: fragments -> smem fp32 staging -> fp16 global (coalesced)
    __syncthreads();                       // everyone done reading stage bufs
    float* cf = reinterpret_cast<float*>(sm);   // 64x128 f32 = 32KB
#pragma unroll
    for (int i = 0; i < 2; i++)
#pragma unroll
        for (int j = 0; j < 2; j++)
            wmma::store_matrix_sync(&cf[(wm*32 + i*16) * 128 + wn*32 + j*16],
                                    c[i][j], 128, wmma::mem_row_major);
    __syncthreads();
    {
        int row = tid >> 2;                // 0..63
        int seg = tid & 3;                 // 32 cols each
        const float* sp = &cf[row * 128 + seg * 32];
        __half hs[32];
#pragma unroll
        for (int q = 0; q < 32; q++) hs[q] = __float2half(sp[q]);
        uint4* dp = reinterpret_cast<uint4*>(&g_h1[(size_t)(row0 + row) * HH + seg * 32]);
        const uint4* s4 = reinterpret_cast<const uint4*>(hs);
        dp[0] = s4[0]; dp[1] = s4[1]; dp[2] = s4[2]; dp[3] = s4[3];
    }
}

// ---------------- fused: agg1 (fp16 gather) + b1 + relu + GEMM2 -> t ----------------
__device__ __forceinline__ void acc_h4(float4& a, uint2 u, float n) {
    __half2 p0 = *reinterpret_cast<__half2*>(&u.x);
    __half2 p1 = *reinterpret_cast<__half2*>(&u.y);
    float2 f0 = __half22float2(p0);
    float2 f1 = __half22float2(p1);
    a.x += f0.x * n; a.y += f0.y * n; a.z += f1.x * n; a.w += f1.y * n;
}

__global__ void k_agg1_gemm2(const float* __restrict__ b1, const float* __restrict__ W2) {
    __shared__ float sW2[CC][HH];
    int tid = threadIdx.x;
    for (int i = tid; i < HH * CC; i += blockDim.x) {
        int j = i / CC, c = i % CC;
        sW2[c][j] = W2[i];
    }
    __syncthreads();

    int lane = tid & 31;
    int node = blockIdx.x * 8 + (tid >> 5);

    float di = g_dinv[node];
    int s0 = g_off[node];
    int cnt = g_deg[node];
    const uint2* h1v = reinterpret_cast<const uint2*>(g_h1);   // 32 uint2 per row

    float4 a0 = make_float4(0.f, 0.f, 0.f, 0.f);
    float4 a1 = make_float4(0.f, 0.f, 0.f, 0.f);
    float4 a2 = make_float4(0.f, 0.f, 0.f, 0.f);
    float4 a3 = make_float4(0.f, 0.f, 0.f, 0.f);
    int k = 0;
    for (; k + 4 <= cnt; k += 4) {          // four gathers in flight
        int sA = g_csr[s0 + k];
        int sB = g_csr[s0 + k + 1];
        int sC = g_csr[s0 + k + 2];
        int sD = g_csr[s0 + k + 3];
        float nA = g_dinv[sA] * di;
        float nB = g_dinv[sB] * di;
        float nC = g_dinv[sC] * di;
        float nD = g_dinv[sD] * di;
        uint2 uA = h1v[sA * 32 + lane];
        uint2 uB = h1v[sB * 32 + lane];
        uint2 uC = h1v[sC * 32 + lane];
        uint2 uD = h1v[sD * 32 + lane];
        acc_h4(a0, uA, nA);
        acc_h4(a1, uB, nB);
        acc_h4(a2, uC, nC);
        acc_h4(a3, uD, nD);
    }
    for (; k < cnt; k++) {
        int s = g_csr[s0 + k];
        float nrm = g_dinv[s] * di;
        acc_h4(a0, h1v[s * 32 + lane], nrm);
    }
    acc_h4(a1, h1v[node * 32 + lane], di * di);   // self loop

    float4 acc = make_float4(a0.x + a1.x + a2.x + a3.x,
                             a0.y + a1.y + a2.y + a3.y,
                             a0.z + a1.z + a2.z + a3.z,
                             a0.w + a1.w + a2.w + a3.w);

    float4 bb = reinterpret_cast<const float4*>(b1)[lane];
    float h0  = fmaxf(acc.x + bb.x, 0.f);
    float h1r = fmaxf(acc.y + bb.y, 0.f);
    float h2r = fmaxf(acc.z + bb.z, 0.f);
    float h3r = fmaxf(acc.w + bb.w, 0.f);

    float myval = 0.f;
#pragma unroll
    for (int c = 0; c < CC; c++) {
        float4 w = reinterpret_cast<float4*>(&sW2[c][0])[lane];
        float p = h0 * w.x + h1r * w.y + h2r * w.z + h3r * w.w;
#pragma unroll
        for (int m = 16; m; m >>= 1) p += __shfl_xor_sync(0xffffffffu, p, m);
        if (lane == c) myval = p;
    }
    if (lane < CC) g_t[node * CC + lane] = myval;
}

// ---------------- fused: agg2 (gather) + b2 + log_softmax -> out ----------------
__global__ void k_agg2_softmax(const float* __restrict__ b2, float* __restrict__ out) {
    int tid = threadIdx.x;
    int lane = tid & 31;
    int node = blockIdx.x * 8 + (tid >> 5);

    float di = g_dinv[node];
    int s0 = g_off[node];
    int cnt = g_deg[node];
    bool act = lane < CC;

    float acc = 0.f;
    for (int k = 0; k < cnt; k++) {
        int s = g_csr[s0 + k];
        float nrm = g_dinv[s] * di;
        if (act) acc += nrm * g_t[s * CC + lane];
    }
    if (act) acc += di * di * g_t[node * CC + lane] + b2[lane];

    const float NEG_INF = __int_as_float(0xff800000u);
    float m = act ? acc : NEG_INF;
#pragma unroll
    for (int mk = 8; mk; mk >>= 1) m = fmaxf(m, __shfl_xor_sync(0xffffffffu, m, mk));
    float e = act ? expf(acc - m) : 0.f;
    float s = e;
#pragma unroll
    for (int mk = 8; mk; mk >>= 1) s += __shfl_xor_sync(0xffffffffu, s, mk);
    float lse = m + logf(s);
    if (act) out[node * CC + lane] = acc - lse;
}

// ---------------- launcher: CSR build forked onto a side stream ----------------
extern "C" void kernel_launch(void* const* d_in, const int* in_sizes, int n_in,
                              void* d_out, int out_size) {
    const float* x  = (const float*)d_in[0];
    const int*   ei = (const int*)d_in[1];
    const float* W1 = (const float*)d_in[2];
    const float* b1 = (const float*)d_in[3];
    const float* W2 = (const float*)d_in[4];
    const float* b2 = (const float*)d_in[5];
    float* out = (float*)d_out;

    const int* src = ei;
    const int* dst = ei + EE;

    cudaFuncSetAttribute(k_gemm1, cudaFuncAttributeMaxDynamicSharedMemorySize, SMEM_BYTES);

    // Fresh handles each call (host objects only; no device allocs, no static guards).
    cudaStream_t s1;
    cudaEvent_t evA, evB;
    cudaStreamCreateWithFlags(&s1, cudaStreamNonBlocking);
    cudaEventCreateWithFlags(&evA, cudaEventDisableTiming);
    cudaEventCreateWithFlags(&evB, cudaEventDisableTiming);

    // fork: CSR build (independent of GEMM) on s1, GEMM on main stream
    cudaEventRecord(evA, 0);
    cudaStreamWaitEvent(s1, evA, 0);

    k_zero_deg<<<(NN + 255) / 256, 256, 0, s1>>>();
    k_deg<<<(EE + 255) / 256, 256, 0, s1>>>(dst);
    k_scan1<<<NBLK, SCAN_B, 0, s1>>>();
    k_scan2<<<1, 128, 0, s1>>>();
    k_finalize<<<(NN + 255) / 256, 256, 0, s1>>>();
    k_fill<<<(EE + 255) / 256, 256, 0, s1>>>(src, dst);
    cudaEventRecord(evB, s1);

    k_gemm1<<<NPAD / 64, 256, SMEM_BYTES>>>(x, W1);     // concurrent with CSR chain

    // join: aggregation needs both GEMM and CSR
    cudaStreamWaitEvent(0, evB, 0);
    k_agg1_gemm2<<<NN / 8, 256>>>(b1, W2);
    k_agg2_softmax<<<NN / 8, 256>>>(b2, out);
}

// round 10
// speedup vs baseline: 1.3980x; 1.0835x over previous
#include <cuda_runtime.h>
#include <cuda_bf16.h>
#include <cuda_fp16.h>
#include <mma.h>
#include <math.h>
#include <stdint.h>

using namespace nvcuda;

#define NN   100000
#define NPAD 100096                 // 1564 * 64
#define EE   1600000
#define FIN  256
#define HH   128
#define CC   10
#define SCAN_B 1024
#define NBLK ((NN + SCAN_B - 1) / SCAN_B)   // 98

#define LDA 40    // 32 + 8 pad (bf16 elems)
#define LDB 136   // 128 + 8 pad
#define A_ELEMS (64 * LDA)                   // 2560
#define B_ELEMS (32 * LDB)                   // 4352
#define STAGE_ELEMS (A_ELEMS + B_ELEMS)      // 6912 (hi only)
#define SMEM_BYTES 32768                     // max(2 stages = 27648, C staging 32768)

// ---------------- scratch (no allocs allowed) ----------------
__device__ int    g_deg[NN];
__device__ int    g_local[NN];
__device__ int    g_bsum[NBLK];
__device__ int    g_boff[NBLK];
__device__ int    g_off[NN];
__device__ int    g_cursor[NN];
__device__ float  g_dinv[NN];
__device__ int    g_csr[EE];
__device__ __half g_h1[(size_t)NPAD * HH];   // 25.6 MB, L2-resident
__device__ float  g_t[NN * CC];

// ---------------- degree ----------------
__global__ void k_zero_deg() {
    int i = blockIdx.x * blockDim.x + threadIdx.x;
    if (i < NN) g_deg[i] = 0;
}
__global__ void k_deg(const int* __restrict__ dst) {
    int e = blockIdx.x * blockDim.x + threadIdx.x;
    if (e < EE) atomicAdd(&g_deg[dst[e]], 1);
}

// ---------------- CSR build ----------------
__global__ void k_scan1() {
    __shared__ int sh[SCAN_B];
    int tid = threadIdx.x;
    int i = blockIdx.x * SCAN_B + tid;
    int v = (i < NN) ? g_deg[i] : 0;
    sh[tid] = v;
    __syncthreads();
    for (int ofs = 1; ofs < SCAN_B; ofs <<= 1) {
        int t = (tid >= ofs) ? sh[tid - ofs] : 0;
        __syncthreads();
        sh[tid] += t;
        __syncthreads();
    }
    if (i < NN) g_local[i] = sh[tid] - v;
    if (tid == SCAN_B - 1) g_bsum[blockIdx.x] = sh[tid];
}
__global__ void k_scan2() {
    __shared__ int sh[128];
    int t = threadIdx.x;
    int v = (t < NBLK) ? g_bsum[t] : 0;
    sh[t] = v;
    __syncthreads();
    for (int o = 1; o < 128; o <<= 1) {
        int x = (t >= o) ? sh[t - o] : 0;
        __syncthreads();
        sh[t] += x;
        __syncthreads();
    }
    if (t < NBLK) g_boff[t] = sh[t] - v;   // exclusive block offsets
}
__global__ void k_finalize() {
    int i = blockIdx.x * blockDim.x + threadIdx.x;
    if (i < NN) {
        int o = g_local[i] + g_boff[i >> 10];
        g_off[i] = o;
        g_cursor[i] = o;
        g_dinv[i] = rsqrtf((float)(g_deg[i] + 1));   // +1 self loop
    }
}
__global__ void k_fill(const int* __restrict__ src, const int* __restrict__ dst) {
    int e = blockIdx.x * blockDim.x + threadIdx.x;
    if (e < EE) {
        int d = dst[e];
        int pos = atomicAdd(&g_cursor[d], 1);
        g_csr[pos] = src[e];
    }
}

// ---------------- GEMM1: h1 = x @ W1, single-pass bf16, double-buffered, fp16 out ----------------
// BM=64, BN=128, BK=32; 256 thr = 8 warps (2m x 4n); warp tile 32x32.
__global__ void __launch_bounds__(256, 3) k_gemm1(const float* __restrict__ x,
                                                  const float* __restrict__ W1) {
    extern __shared__ __nv_bfloat16 sm[];
    int tid = threadIdx.x;
    int wid = tid >> 5;
    int wm = wid & 1;         // 0..1  (m)
    int wn = wid >> 1;        // 0..3  (n)
    int row0 = blockIdx.x * 64;

    int arow[2], ac4[2], agr[2], brow[4], bc4[4];
#pragma unroll
    for (int r = 0; r < 2; r++) {
        int f4 = tid + r * 256;
        arow[r] = f4 >> 3;  ac4[r] = (f4 & 7) * 4;
        int gr = row0 + arow[r]; if (gr >= NN) gr = NN - 1;
        agr[r] = gr;
    }
#pragma unroll
    for (int r = 0; r < 4; r++) {
        int f4 = tid + r * 256;
        brow[r] = f4 >> 5;  bc4[r] = (f4 & 31) * 4;
    }

    wmma::fragment<wmma::accumulator, 16, 16, 16, float> c[2][2];
#pragma unroll
    for (int i = 0; i < 2; i++)
#pragma unroll
        for (int j = 0; j < 2; j++) wmma::fill_fragment(c[i][j], 0.f);

    float4 pa[2], pb[4];

    auto load_regs = [&](int t) {
#pragma unroll
        for (int r = 0; r < 2; r++)
            pa[r] = *reinterpret_cast<const float4*>(&x[(size_t)agr[r] * FIN + t * 32 + ac4[r]]);
#pragma unroll
        for (int r = 0; r < 4; r++)
            pb[r] = *reinterpret_cast<const float4*>(&W1[(size_t)(t * 32 + brow[r]) * HH + bc4[r]]);
    };
    auto store_smem = [&](int buf) {
        __nv_bfloat16* Ah = sm + buf * STAGE_ELEMS;
        __nv_bfloat16* Bh = Ah + A_ELEMS;
#pragma unroll
        for (int r = 0; r < 2; r++) {
            int o = arow[r] * LDA + ac4[r];
            Ah[o+0] = __float2bfloat16(pa[r].x);
            Ah[o+1] = __float2bfloat16(pa[r].y);
            Ah[o+2] = __float2bfloat16(pa[r].z);
            Ah[o+3] = __float2bfloat16(pa[r].w);
        }
#pragma unroll
        for (int r = 0; r < 4; r++) {
            int o = brow[r] * LDB + bc4[r];
            Bh[o+0] = __float2bfloat16(pb[r].x);
            Bh[o+1] = __float2bfloat16(pb[r].y);
            Bh[o+2] = __float2bfloat16(pb[r].z);
            Bh[o+3] = __float2bfloat16(pb[r].w);
        }
    };
    auto do_mma = [&](int buf) {
        __nv_bfloat16* Ah = sm + buf * STAGE_ELEMS;
        __nv_bfloat16* Bh = Ah + A_ELEMS;
#pragma unroll
        for (int kk = 0; kk < 32; kk += 16) {
            wmma::fragment<wmma::matrix_a, 16, 16, 16, __nv_bfloat16, wmma::row_major> ah[2];
            wmma::fragment<wmma::matrix_b, 16, 16, 16, __nv_bfloat16, wmma::row_major> bh[2];
#pragma unroll
            for (int i = 0; i < 2; i++)
                wmma::load_matrix_sync(ah[i], &Ah[(wm*32 + i*16)*LDA + kk], LDA);
#pragma unroll
            for (int j = 0; j < 2; j++)
                wmma::load_matrix_sync(bh[j], &Bh[kk*LDB + wn*32 + j*16], LDB);
#pragma unroll
            for (int i = 0; i < 2; i++)
#pragma unroll
                for (int j = 0; j < 2; j++)
                    wmma::mma_sync(c[i][j], ah[i], bh[j], c[i][j]);
        }
    };

    load_regs(0);
    store_smem(0);
    __syncthreads();

    const int NT = FIN / 32;   // 8 k-steps
    for (int t = 0; t < NT; t++) {
        if (t + 1 < NT) load_regs(t + 1);
        do_mma(t & 1);
        if (t + 1 < NT) {
            __syncthreads();
            store_smem((t + 1) & 1);
            __syncthreads();
        }
    }

    // epilogue: fragments -> smem fp32 staging -> fp16 global (coalesced)
    __syncthreads();
    float* cf = reinterpret_cast<float*>(sm);   // 64x128 f32 = 32KB
#pragma unroll
    for (int i = 0; i < 2; i++)
#pragma unroll
        for (int j = 0; j < 2; j++)
            wmma::store_matrix_sync(&cf[(wm*32 + i*16) * 128 + wn*32 + j*16],
                                    c[i][j], 128, wmma::mem_row_major);
    __syncthreads();
    {
        int row = tid >> 2;                // 0..63
        int seg = tid & 3;                 // 32 cols each
        const float* sp = &cf[row * 128 + seg * 32];
        __half hs[32];
#pragma unroll
        for (int q = 0; q < 32; q++) hs[q] = __float2half(sp[q]);
        uint4* dp = reinterpret_cast<uint4*>(&g_h1[(size_t)(row0 + row) * HH + seg * 32]);
        const uint4* s4 = reinterpret_cast<const uint4*>(hs);
        dp[0] = s4[0]; dp[1] = s4[1]; dp[2] = s4[2]; dp[3] = s4[3];
    }
}

// ---------------- fused: agg1 (fp16 gather) + b1 + relu + GEMM2 -> t ----------------
__device__ __forceinline__ void acc_h4(float4& a, uint2 u, float n) {
    __half2 p0 = *reinterpret_cast<__half2*>(&u.x);
    __half2 p1 = *reinterpret_cast<__half2*>(&u.y);
    float2 f0 = __half22float2(p0);
    float2 f1 = __half22float2(p1);
    a.x += f0.x * n; a.y += f0.y * n; a.z += f1.x * n; a.w += f1.y * n;
}

__global__ void k_agg1_gemm2(const float* __restrict__ b1, const float* __restrict__ W2) {
    __shared__ float sW2[CC][HH];
    int tid = threadIdx.x;
    for (int i = tid; i < HH * CC; i += blockDim.x) {
        int j = i / CC, c = i % CC;
        sW2[c][j] = W2[i];
    }
    __syncthreads();

    int lane = tid & 31;
    int node = blockIdx.x * 8 + (tid >> 5);

    float di = g_dinv[node];
    int s0 = g_off[node];
    int cnt = g_deg[node];
    const uint2* h1v = reinterpret_cast<const uint2*>(g_h1);   // 32 uint2 per row

    float4 a0 = make_float4(0.f, 0.f, 0.f, 0.f);
    float4 a1 = make_float4(0.f, 0.f, 0.f, 0.f);
    float4 a2 = make_float4(0.f, 0.f, 0.f, 0.f);
    float4 a3 = make_float4(0.f, 0.f, 0.f, 0.f);
    int k = 0;
    for (; k + 4 <= cnt; k += 4) {          // four gathers in flight
        int sA = g_csr[s0 + k];
        int sB = g_csr[s0 + k + 1];
        int sC = g_csr[s0 + k + 2];
        int sD = g_csr[s0 + k + 3];
        float nA = g_dinv[sA] * di;
        float nB = g_dinv[sB] * di;
        float nC = g_dinv[sC] * di;
        float nD = g_dinv[sD] * di;
        uint2 uA = h1v[sA * 32 + lane];
        uint2 uB = h1v[sB * 32 + lane];
        uint2 uC = h1v[sC * 32 + lane];
        uint2 uD = h1v[sD * 32 + lane];
        acc_h4(a0, uA, nA);
        acc_h4(a1, uB, nB);
        acc_h4(a2, uC, nC);
        acc_h4(a3, uD, nD);
    }
    for (; k < cnt; k++) {
        int s = g_csr[s0 + k];
        float nrm = g_dinv[s] * di;
        acc_h4(a0, h1v[s * 32 + lane], nrm);
    }
    acc_h4(a1, h1v[node * 32 + lane], di * di);   // self loop

    float4 acc = make_float4(a0.x + a1.x + a2.x + a3.x,
                             a0.y + a1.y + a2.y + a3.y,
                             a0.z + a1.z + a2.z + a3.z,
                             a0.w + a1.w + a2.w + a3.w);

    float4 bb = reinterpret_cast<const float4*>(b1)[lane];
    float h0  = fmaxf(acc.x + bb.x, 0.f);
    float h1r = fmaxf(acc.y + bb.y, 0.f);
    float h2r = fmaxf(acc.z + bb.z, 0.f);
    float h3r = fmaxf(acc.w + bb.w, 0.f);

    float myval = 0.f;
#pragma unroll
    for (int c = 0; c < CC; c++) {
        float4 w = reinterpret_cast<float4*>(&sW2[c][0])[lane];
        float p = h0 * w.x + h1r * w.y + h2r * w.z + h3r * w.w;
#pragma unroll
        for (int m = 16; m; m >>= 1) p += __shfl_xor_sync(0xffffffffu, p, m);
        if (lane == c) myval = p;
    }
    if (lane < CC) g_t[node * CC + lane] = myval;
}

// ---------------- fused: agg2 (gather) + b2 + log_softmax -> out ----------------
__global__ void k_agg2_softmax(const float* __restrict__ b2, float* __restrict__ out) {
    int tid = threadIdx.x;
    int lane = tid & 31;
    int node = blockIdx.x * 8 + (tid >> 5);

    float di = g_dinv[node];
    int s0 = g_off[node];
    int cnt = g_deg[node];
    bool act = lane < CC;

    float acc = 0.f;
    for (int k = 0; k < cnt; k++) {
        int s = g_csr[s0 + k];
        float nrm = g_dinv[s] * di;
        if (act) acc += nrm * g_t[s * CC + lane];
    }
    if (act) acc += di * di * g_t[node * CC + lane] + b2[lane];

    const float NEG_INF = __int_as_float(0xff800000u);
    float m = act ? acc : NEG_INF;
#pragma unroll
    for (int mk = 8; mk; mk >>= 1) m = fmaxf(m, __shfl_xor_sync(0xffffffffu, m, mk));
    float e = act ? expf(acc - m) : 0.f;
    float s = e;
#pragma unroll
    for (int mk = 8; mk; mk >>= 1) s += __shfl_xor_sync(0xffffffffu, s, mk);
    float lse = m + logf(s);
    if (act) out[node * CC + lane] = acc - lse;
}

// ---------------- launcher: CSR build forked onto a side stream ----------------
extern "C" void kernel_launch(void* const* d_in, const int* in_sizes, int n_in,
                              void* d_out, int out_size) {
    const float* x  = (const float*)d_in[0];
    const int*   ei = (const int*)d_in[1];
    const float* W1 = (const float*)d_in[2];
    const float* b1 = (const float*)d_in[3];
    const float* W2 = (const float*)d_in[4];
    const float* b2 = (const float*)d_in[5];
    float* out = (float*)d_out;

    const int* src = ei;
    const int* dst = ei + EE;

    cudaFuncSetAttribute(k_gemm1, cudaFuncAttributeMaxDynamicSharedMemorySize, SMEM_BYTES);

    cudaStream_t s1;
    cudaEvent_t evA, evB;
    cudaStreamCreateWithFlags(&s1, cudaStreamNonBlocking);
    cudaEventCreateWithFlags(&evA, cudaEventDisableTiming);
    cudaEventCreateWithFlags(&evB, cudaEventDisableTiming);

    // fork: CSR build (independent of GEMM) on s1, GEMM on main stream
    cudaEventRecord(evA, 0);
    cudaStreamWaitEvent(s1, evA, 0);

    k_zero_deg<<<(NN + 255) / 256, 256, 0, s1>>>();
    k_deg<<<(EE + 255) / 256, 256, 0, s1>>>(dst);
    k_scan1<<<NBLK, SCAN_B, 0, s1>>>();
    k_scan2<<<1, 128, 0, s1>>>();
    k_finalize<<<(NN + 255) / 256, 256, 0, s1>>>();
    k_fill<<<(EE + 255) / 256, 256, 0, s1>>>(src, dst);
    cudaEventRecord(evB, s1);

    k_gemm1<<<NPAD / 64, 256, SMEM_BYTES>>>(x, W1);     // concurrent with CSR chain

    // join: aggregation needs both GEMM and CSR
    cudaStreamWaitEvent(0, evB, 0);
    k_agg1_gemm2<<<NN / 8, 256>>>(b1, W2);
    k_agg2_softmax<<<NN / 8, 256>>>(b2, out);
}

// round 13
// speedup vs baseline: 1.4744x; 1.0546x over previous
#include <cuda_runtime.h>
#include <cuda_bf16.h>
#include <cuda_fp16.h>
#include <mma.h>
#include <math.h>
#include <stdint.h>

using namespace nvcuda;

#define NN   100000
#define NPAD 100096                 // 1564 * 64
#define EE   1600000
#define FIN  256
#define HH   128
#define CC   10
#define SCAN_B 1024
#define NBLK ((NN + SCAN_B - 1) / SCAN_B)   // 98

#define LDA 40    // 32 + 8 pad (bf16 elems)
#define LDB 136   // 128 + 8 pad
#define A_ELEMS (64 * LDA)                   // 2560
#define B_ELEMS (32 * LDB)                   // 4352
#define STAGE_ELEMS (A_ELEMS + B_ELEMS)      // 6912
#define SMEM_BYTES 32768                     // max(2 stages = 27648, C staging 32768)

// ---------------- scratch (no allocs allowed) ----------------
__device__ int    g_deg[NN];
__device__ int    g_local[NN];
__device__ int    g_bsum[NBLK];
__device__ int    g_boff[NBLK];
__device__ int    g_off[NN];
__device__ int    g_cursor[NN];
__device__ float  g_dinv[NN];
__device__ int    g_csr[EE];
__device__ __half g_h1[(size_t)NPAD * HH];   // 25.6 MB, L2-resident
__device__ float  g_t[NN * CC];

// ---------------- degree ----------------
__global__ void k_zero_deg() {
    int i = blockIdx.x * blockDim.x + threadIdx.x;
    if (i < NN) g_deg[i] = 0;
}
__global__ void k_deg(const int* __restrict__ dst) {
    int e = blockIdx.x * blockDim.x + threadIdx.x;
    if (e < EE) atomicAdd(&g_deg[dst[e]], 1);
}

// ---------------- CSR build ----------------
__global__ void k_scan1() {
    __shared__ int sh[SCAN_B];
    int tid = threadIdx.x;
    int i = blockIdx.x * SCAN_B + tid;
    int v = (i < NN) ? g_deg[i] : 0;
    sh[tid] = v;
    __syncthreads();
    for (int ofs = 1; ofs < SCAN_B; ofs <<= 1) {
        int t = (tid >= ofs) ? sh[tid - ofs] : 0;
        __syncthreads();
        sh[tid] += t;
        __syncthreads();
    }
    if (i < NN) g_local[i] = sh[tid] - v;
    if (tid == SCAN_B - 1) g_bsum[blockIdx.x] = sh[tid];
}
__global__ void k_scan2() {
    __shared__ int sh[128];
    int t = threadIdx.x;
    int v = (t < NBLK) ? g_bsum[t] : 0;
    sh[t] = v;
    __syncthreads();
    for (int o = 1; o < 128; o <<= 1) {
        int x = (t >= o) ? sh[t - o] : 0;
        __syncthreads();
        sh[t] += x;
        __syncthreads();
    }
    if (t < NBLK) g_boff[t] = sh[t] - v;   // exclusive block offsets
}
__global__ void k_finalize() {
    int i = blockIdx.x * blockDim.x + threadIdx.x;
    if (i < NN) {
        int o = g_local[i] + g_boff[i >> 10];
        g_off[i] = o;
        g_cursor[i] = o;
        g_dinv[i] = rsqrtf((float)(g_deg[i] + 1));   // +1 self loop
    }
}
__global__ void k_fill(const int* __restrict__ src, const int* __restrict__ dst) {
    int e = blockIdx.x * blockDim.x + threadIdx.x;
    if (e < EE) {
        int d = dst[e];
        int pos = atomicAdd(&g_cursor[d], 1);
        g_csr[pos] = src[e];
    }
}

// ---------------- GEMM1: h1 = x @ W1, bf16, double-buffered, one sync/k-step ----------------
__global__ void __launch_bounds__(256, 3) k_gemm1(const float* __restrict__ x,
                                                  const float* __restrict__ W1) {
    extern __shared__ __nv_bfloat16 sm[];
    int tid = threadIdx.x;
    int wid = tid >> 5;
    int wm = wid & 1;         // 0..1  (m)
    int wn = wid >> 1;        // 0..3  (n)
    int row0 = blockIdx.x * 64;

    int arow[2], ac4[2], agr[2], brow[4], bc4[4];
#pragma unroll
    for (int r = 0; r < 2; r++) {
        int f4 = tid + r * 256;
        arow[r] = f4 >> 3;  ac4[r] = (f4 & 7) * 4;
        int gr = row0 + arow[r]; if (gr >= NN) gr = NN - 1;
        agr[r] = gr;
    }
#pragma unroll
    for (int r = 0; r < 4; r++) {
        int f4 = tid + r * 256;
        brow[r] = f4 >> 5;  bc4[r] = (f4 & 31) * 4;
    }

    wmma::fragment<wmma::accumulator, 16, 16, 16, float> c[2][2];
#pragma unroll
    for (int i = 0; i < 2; i++)
#pragma unroll
        for (int j = 0; j < 2; j++) wmma::fill_fragment(c[i][j], 0.f);

    float4 pa[2], pb[4];

    auto load_regs = [&](int t) {
#pragma unroll
        for (int r = 0; r < 2; r++)
            pa[r] = *reinterpret_cast<const float4*>(&x[(size_t)agr[r] * FIN + t * 32 + ac4[r]]);
#pragma unroll
        for (int r = 0; r < 4; r++)
            pb[r] = *reinterpret_cast<const float4*>(&W1[(size_t)(t * 32 + brow[r]) * HH + bc4[r]]);
    };
    auto store_smem = [&](int buf) {
        __nv_bfloat16* Ah = sm + buf * STAGE_ELEMS;
        __nv_bfloat16* Bh = Ah + A_ELEMS;
#pragma unroll
        for (int r = 0; r < 2; r++) {
            int o = arow[r] * LDA + ac4[r];
            Ah[o+0] = __float2bfloat16(pa[r].x);
            Ah[o+1] = __float2bfloat16(pa[r].y);
            Ah[o+2] = __float2bfloat16(pa[r].z);
            Ah[o+3] = __float2bfloat16(pa[r].w);
        }
#pragma unroll
        for (int r = 0; r < 4; r++) {
            int o = brow[r] * LDB + bc4[r];
            Bh[o+0] = __float2bfloat16(pb[r].x);
            Bh[o+1] = __float2bfloat16(pb[r].y);
            Bh[o+2] = __float2bfloat16(pb[r].z);
            Bh[o+3] = __float2bfloat16(pb[r].w);
        }
    };
    auto do_mma = [&](int buf) {
        __nv_bfloat16* Ah = sm + buf * STAGE_ELEMS;
        __nv_bfloat16* Bh = Ah + A_ELEMS;
#pragma unroll
        for (int kk = 0; kk < 32; kk += 16) {
            wmma::fragment<wmma::matrix_a, 16, 16, 16, __nv_bfloat16, wmma::row_major> ah[2];
            wmma::fragment<wmma::matrix_b, 16, 16, 16, __nv_bfloat16, wmma::row_major> bh[2];
#pragma unroll
            for (int i = 0; i < 2; i++)
                wmma::load_matrix_sync(ah[i], &Ah[(wm*32 + i*16)*LDA + kk], LDA);
#pragma unroll
            for (int j = 0; j < 2; j++)
                wmma::load_matrix_sync(bh[j], &Bh[kk*LDB + wn*32 + j*16], LDB);
#pragma unroll
            for (int i = 0; i < 2; i++)
#pragma unroll
                for (int j = 0; j < 2; j++)
                    wmma::mma_sync(c[i][j], ah[i], bh[j], c[i][j]);
        }
    };

    load_regs(0);
    store_smem(0);
    __syncthreads();

    const int NT = FIN / 32;   // 8 k-steps
    // One sync per k-step: stores target the opposite buffer; reads of that
    // buffer finished before the *previous* iteration's sync.
    for (int t = 0; t < NT; t++) {
        if (t + 1 < NT) load_regs(t + 1);
        do_mma(t & 1);
        if (t + 1 < NT) {
            store_smem((t + 1) & 1);
            __syncthreads();
        }
    }

    // epilogue: fragments -> smem fp32 staging -> fp16 global (coalesced)
    __syncthreads();
    float* cf = reinterpret_cast<float*>(sm);   // 64x128 f32 = 32KB
#pragma unroll
    for (int i = 0; i < 2; i++)
#pragma unroll
        for (int j = 0; j < 2; j++)
            wmma::store_matrix_sync(&cf[(wm*32 + i*16) * 128 + wn*32 + j*16],
                                    c[i][j], 128, wmma::mem_row_major);
    __syncthreads();
    {
        int row = tid >> 2;                // 0..63
        int seg = tid & 3;                 // 32 cols each
        const float* sp = &cf[row * 128 + seg * 32];
        __half hs[32];
#pragma unroll
        for (int q = 0; q < 32; q++) hs[q] = __float2half(sp[q]);
        uint4* dp = reinterpret_cast<uint4*>(&g_h1[(size_t)(row0 + row) * HH + seg * 32]);
        const uint4* s4 = reinterpret_cast<const uint4*>(hs);
        dp[0] = s4[0]; dp[1] = s4[1]; dp[2] = s4[2]; dp[3] = s4[3];
    }
}

// ---------------- fused: agg1 (fp16 gather) + b1 + relu + GEMM2 -> t ----------------
__device__ __forceinline__ void acc_h4(float4& a, uint2 u, float n) {
    __half2 p0 = *reinterpret_cast<__half2*>(&u.x);
    __half2 p1 = *reinterpret_cast<__half2*>(&u.y);
    float2 f0 = __half22float2(p0);
    float2 f1 = __half22float2(p1);
    a.x += f0.x * n; a.y += f0.y * n; a.z += f1.x * n; a.w += f1.y * n;
}

__global__ void k_agg1_gemm2(const float* __restrict__ b1, const float* __restrict__ W2) {
    __shared__ float sW2[CC][HH];
    int tid = threadIdx.x;
    for (int i = tid; i < HH * CC; i += blockDim.x) {
        int j = i / CC, c = i % CC;
        sW2[c][j] = W2[i];
    }
    __syncthreads();

    int lane = tid & 31;
    int node = blockIdx.x * 8 + (tid >> 5);

    float di = g_dinv[node];
    int s0 = g_off[node];
    int cnt = g_deg[node];
    const uint2* h1v = reinterpret_cast<const uint2*>(g_h1);

    float4 a0 = make_float4(0.f, 0.f, 0.f, 0.f);
    float4 a1 = make_float4(0.f, 0.f, 0.f, 0.f);
    float4 a2 = make_float4(0.f, 0.f, 0.f, 0.f);
    float4 a3 = make_float4(0.f, 0.f, 0.f, 0.f);
    int k = 0;
    for (; k + 4 <= cnt; k += 4) {
        int sA = g_csr[s0 + k];
        int sB = g_csr[s0 + k + 1];
        int sC = g_csr[s0 + k + 2];
        int sD = g_csr[s0 + k + 3];
        float nA = g_dinv[sA] * di;
        float nB = g_dinv[sB] * di;
        float nC = g_dinv[sC] * di;
        float nD = g_dinv[sD] * di;
        uint2 uA = h1v[sA * 32 + lane];
        uint2 uB = h1v[sB * 32 + lane];
        uint2 uC = h1v[sC * 32 + lane];
        uint2 uD = h1v[sD * 32 + lane];
        acc_h4(a0, uA, nA);
        acc_h4(a1, uB, nB);
        acc_h4(a2, uC, nC);
        acc_h4(a3, uD, nD);
    }
    for (; k < cnt; k++) {
        int s = g_csr[s0 + k];
        float nrm = g_dinv[s] * di;
        acc_h4(a0, h1v[s * 32 + lane], nrm);
    }
    acc_h4(a1, h1v[node * 32 + lane], di * di);   // self loop

    float4 acc = make_float4(a0.x + a1.x + a2.x + a3.x,
                             a0.y + a1.y + a2.y + a3.y,
                             a0.z + a1.z + a2.z + a3.z,
                             a0.w + a1.w + a2.w + a3.w);

    float4 bb = reinterpret_cast<const float4*>(b1)[lane];
    float h0  = fmaxf(acc.x + bb.x, 0.f);
    float h1r = fmaxf(acc.y + bb.y, 0.f);
    float h2r = fmaxf(acc.z + bb.z, 0.f);
    float h3r = fmaxf(acc.w + bb.w, 0.f);

    float myval = 0.f;
#pragma unroll
    for (int c = 0; c < CC; c++) {
        float4 w = reinterpret_cast<float4*>(&sW2[c][0])[lane];
        float p = h0 * w.x + h1r * w.y + h2r * w.z + h3r * w.w;
#pragma unroll
        for (int m = 16; m; m >>= 1) p += __shfl_xor_sync(0xffffffffu, p, m);
        if (lane == c) myval = p;
    }
    if (lane < CC) g_t[node * CC + lane] = myval;
}

// ---------------- fused: agg2 (gather, 3 edges/iter) + b2 + log_softmax -> out ----------------
// lanes 0-9 / 10-19 / 20-29 each process one edge's 10 classes -> 3x MLP.
__global__ void k_agg2_softmax(const float* __restrict__ b2, float* __restrict__ out) {
    int tid = threadIdx.x;
    int lane = tid & 31;
    int node = blockIdx.x * 8 + (tid >> 5);

    float di = g_dinv[node];
    int s0 = g_off[node];
    int cnt = g_deg[node];

    int grp = lane / 10;                 // 0..2 (3 for lanes 30,31)
    int cls = lane - grp * 10;           // 0..9
    bool act3 = lane < 30;
    int gsafe = act3 ? grp : 0;

    float acc = 0.f;
    int k = 0;
    for (; k + 3 <= cnt; k += 3) {
        int s = g_csr[s0 + k + gsafe];
        float nrm = g_dinv[s] * di;
        float tv = g_t[s * CC + cls];
        if (act3) acc += nrm * tv;
    }
    for (; k < cnt; k++) {               // remainder on group 0
        int s = g_csr[s0 + k];
        float nrm = g_dinv[s] * di;
        if (grp == 0) acc += nrm * g_t[s * CC + cls];
    }
    if (grp == 0) acc += di * di * g_t[node * CC + cls];   // self loop

    // combine the three groups into lanes 0-9
    float v10 = __shfl_sync(0xffffffffu, acc, lane + 10);
    float v20 = __shfl_sync(0xffffffffu, acc, lane + 20);
    bool act = lane < CC;
    if (act) acc += v10 + v20;
    if (act) acc += b2[cls];

    const float NEG_INF = __int_as_float(0xff800000u);
    float m = act ? acc : NEG_INF;
#pragma unroll
    for (int mk = 8; mk; mk >>= 1) m = fmaxf(m, __shfl_xor_sync(0xffffffffu, m, mk));
    float e = act ? expf(acc - m) : 0.f;
    float s = e;
#pragma unroll
    for (int mk = 8; mk; mk >>= 1) s += __shfl_xor_sync(0xffffffffu, s, mk);
    float lse = m + logf(s);
    if (act) out[node * CC + lane] = acc - lse;
}

// ---------------- launcher: CSR build forked onto a side stream ----------------
extern "C" void kernel_launch(void* const* d_in, const int* in_sizes, int n_in,
                              void* d_out, int out_size) {
    const float* x  = (const float*)d_in[0];
    const int*   ei = (const int*)d_in[1];
    const float* W1 = (const float*)d_in[2];
    const float* b1 = (const float*)d_in[3];
    const float* W2 = (const float*)d_in[4];
    const float* b2 = (const float*)d_in[5];
    float* out = (float*)d_out;

    const int* src = ei;
    const int* dst = ei + EE;

    cudaFuncSetAttribute(k_gemm1, cudaFuncAttributeMaxDynamicSharedMemorySize, SMEM_BYTES);

    cudaStream_t s1;
    cudaEvent_t evA, evB;
    cudaStreamCreateWithFlags(&s1, cudaStreamNonBlocking);
    cudaEventCreateWithFlags(&evA, cudaEventDisableTiming);
    cudaEventCreateWithFlags(&evB, cudaEventDisableTiming);

    // fork: CSR build (independent of GEMM) on s1, GEMM on main stream
    cudaEventRecord(evA, 0);
    cudaStreamWaitEvent(s1, evA, 0);

    k_zero_deg<<<(NN + 255) / 256, 256, 0, s1>>>();
    k_deg<<<(EE + 255) / 256, 256, 0, s1>>>(dst);
    k_scan1<<<NBLK, SCAN_B, 0, s1>>>();
    k_scan2<<<1, 128, 0, s1>>>();
    k_finalize<<<(NN + 255) / 256, 256, 0, s1>>>();
    k_fill<<<(EE + 255) / 256, 256, 0, s1>>>(src, dst);
    cudaEventRecord(evB, s1);

    k_gemm1<<<NPAD / 64, 256, SMEM_BYTES>>>(x, W1);     // concurrent with CSR chain

    // join: aggregation needs both GEMM and CSR
    cudaStreamWaitEvent(0, evB, 0);
    k_agg1_gemm2<<<NN / 8, 256>>>(b1, W2);
    k_agg2_softmax<<<NN / 8, 256>>>(b2, out);
}